// round 1
// baseline (speedup 1.0000x reference)
#include <cuda_runtime.h>

// ---------------------------------------------------------------------------
// GATNet: 2-layer GAT, N=50000 nodes, E=800000 edges (+N self loops)
// Layer1: heads=8, out=8 (concat -> 64). Layer2: heads=1, out=16.
// Pipeline (all f32):
//   xl = x @ W1                      [N,64]
//   a_src1/a_dst1 per (n,h)          [N,8]
//   edge pass A: denom1[d,h] += exp(leaky(as[s,h]+ad[d,h]))
//   edge pass B: h[d,:] += xl[s,:] * coef(e,h)
//   hl2 = (h+b1) @ W2, a_src2/a_dst2 [N,16],[N]
//   edge pass A2 / B2 (heads=1)
//   out = log_softmax(elu(o2 + b2))
// Softmax max-subtraction skipped: shift-invariant, |alpha| is O(1) here.
// ---------------------------------------------------------------------------

#define NMAX 50000

__device__ __align__(16) float g_xl [NMAX * 64];
__device__ __align__(16) float g_as1[NMAX * 8];
__device__ __align__(16) float g_ad1[NMAX * 8];
__device__ __align__(16) float g_den1[NMAX * 8];
__device__ __align__(16) float g_h  [NMAX * 64];
__device__ __align__(16) float g_hl2[NMAX * 16];
__device__ __align__(16) float g_as2[NMAX];
__device__ __align__(16) float g_ad2[NMAX];
__device__ __align__(16) float g_den2[NMAX];
__device__ __align__(16) float g_o2 [NMAX * 16];

__device__ __forceinline__ float leaky02(float a) {
    // leaky_relu slope 0.2: for a<0, 0.2a > a; for a>=0, a >= 0.2a
    return fmaxf(a, 0.2f * a);
}

__device__ __forceinline__ void atomicAdd4(float* p, float4 v) {
#if defined(__CUDA_ARCH__) && (__CUDA_ARCH__ >= 900)
    atomicAdd(reinterpret_cast<float4*>(p), v);
#else
    atomicAdd(p + 0, v.x); atomicAdd(p + 1, v.y);
    atomicAdd(p + 2, v.z); atomicAdd(p + 3, v.w);
#endif
}

// ------------------------------- zero scratch ------------------------------
__global__ void k_zero(int N) {
    int total = N * 64 + N * 8 + N + N * 16;  // g_h, g_den1, g_den2, g_o2
    for (int i = blockIdx.x * blockDim.x + threadIdx.x; i < total;
         i += gridDim.x * blockDim.x) {
        int j = i;
        if (j < N * 64) { g_h[j] = 0.f; continue; }
        j -= N * 64;
        if (j < N * 8) { g_den1[j] = 0.f; continue; }
        j -= N * 8;
        if (j < N) { g_den2[j] = 0.f; continue; }
        j -= N;
        g_o2[j] = 0.f;
    }
}

// ------------------------------- GEMM1: xl = x @ W1 ------------------------
// x [N,512] row-major, W1 [512,64] row-major, out g_xl [N,64].
// Block: 64 rows x 64 cols, 256 threads, 4x4 micro-tile, BK=32.
__global__ __launch_bounds__(256) void k_gemm1(const float* __restrict__ X,
                                               const float* __restrict__ W,
                                               int N) {
    __shared__ float sA[32][68];   // [k][m], padded
    __shared__ float sB[32][64];   // [k][n]
    const int block_m = blockIdx.x * 64;
    const int tid = threadIdx.x;
    const int tn = tid & 15, tm = tid >> 4;

    float acc[4][4];
#pragma unroll
    for (int i = 0; i < 4; i++)
#pragma unroll
        for (int j = 0; j < 4; j++) acc[i][j] = 0.f;

    const int ca = tid & 31, ra0 = tid >> 5;   // A load: col k, base row
    const int nb = tid & 63, kb0 = tid >> 6;   // B load: col n, base k

    for (int k0 = 0; k0 < 512; k0 += 32) {
#pragma unroll
        for (int p = 0; p < 8; p++) {
            int r = ra0 + p * 8;
            int gr = block_m + r;
            float v = (gr < N) ? X[(size_t)gr * 512 + (k0 + ca)] : 0.f;
            sA[ca][r] = v;
        }
#pragma unroll
        for (int p = 0; p < 8; p++) {
            int kk = kb0 + p * 4;
            sB[kk][nb] = W[(size_t)(k0 + kk) * 64 + nb];
        }
        __syncthreads();
#pragma unroll
        for (int kk = 0; kk < 32; kk++) {
            float4 a = *(const float4*)&sA[kk][tm * 4];
            float4 b = *(const float4*)&sB[kk][tn * 4];
            acc[0][0] += a.x * b.x; acc[0][1] += a.x * b.y;
            acc[0][2] += a.x * b.z; acc[0][3] += a.x * b.w;
            acc[1][0] += a.y * b.x; acc[1][1] += a.y * b.y;
            acc[1][2] += a.y * b.z; acc[1][3] += a.y * b.w;
            acc[2][0] += a.z * b.x; acc[2][1] += a.z * b.y;
            acc[2][2] += a.z * b.z; acc[2][3] += a.z * b.w;
            acc[3][0] += a.w * b.x; acc[3][1] += a.w * b.y;
            acc[3][2] += a.w * b.z; acc[3][3] += a.w * b.w;
        }
        __syncthreads();
    }
#pragma unroll
    for (int i = 0; i < 4; i++) {
        int row = block_m + tm * 4 + i;
        if (row < N) {
            float4 o = make_float4(acc[i][0], acc[i][1], acc[i][2], acc[i][3]);
            *(float4*)&g_xl[(size_t)row * 64 + tn * 4] = o;
        }
    }
}

// --------------------- per-node attention logits (layer1) ------------------
__global__ void k_node1(const float* __restrict__ att_s,
                        const float* __restrict__ att_d, int N) {
    int n = blockIdx.x * blockDim.x + threadIdx.x;
    if (n >= N) return;
    const float* xl = g_xl + (size_t)n * 64;
#pragma unroll
    for (int h = 0; h < 8; h++) {
        float s = 0.f, d = 0.f;
#pragma unroll
        for (int c = 0; c < 8; c++) {
            float v = xl[h * 8 + c];
            s += v * __ldg(att_s + h * 8 + c);
            d += v * __ldg(att_d + h * 8 + c);
        }
        g_as1[n * 8 + h] = s;
        g_ad1[n * 8 + h] = d;
    }
}

// --------------------------- edge pass A (layer1) --------------------------
__global__ void k_edge1a(const int* __restrict__ ei, int E, int N) {
    int e = blockIdx.x * blockDim.x + threadIdx.x;
    int E2 = E + N;
    if (e >= E2) return;
    int s, d;
    if (e < E) { s = ei[e]; d = ei[E + e]; } else { s = d = e - E; }
    float w[8];
#pragma unroll
    for (int h = 0; h < 8; h++) {
        float a = g_as1[s * 8 + h] + g_ad1[d * 8 + h];
        w[h] = __expf(leaky02(a));
    }
    atomicAdd4(&g_den1[d * 8 + 0], make_float4(w[0], w[1], w[2], w[3]));
    atomicAdd4(&g_den1[d * 8 + 4], make_float4(w[4], w[5], w[6], w[7]));
}

// --------------------------- edge pass B (layer1) --------------------------
// one thread per (edge, head): gathers 32B of xl, 2 float4 atomic adds
__global__ void k_edge1b(const int* __restrict__ ei, int E, int N) {
    int tid = blockIdx.x * blockDim.x + threadIdx.x;
    int E2 = E + N;
    int e = tid >> 3, h = tid & 7;
    if (e >= E2) return;
    int s, d;
    if (e < E) { s = ei[e]; d = ei[E + e]; } else { s = d = e - E; }
    float a = g_as1[s * 8 + h] + g_ad1[d * 8 + h];
    float coef = __expf(leaky02(a)) / (g_den1[d * 8 + h] + 1e-16f);
    const float4* xs = (const float4*)(g_xl + (size_t)s * 64 + h * 8);
    float4 v0 = xs[0], v1 = xs[1];
    v0.x *= coef; v0.y *= coef; v0.z *= coef; v0.w *= coef;
    v1.x *= coef; v1.y *= coef; v1.z *= coef; v1.w *= coef;
    float* dst = g_h + (size_t)d * 64 + h * 8;
    atomicAdd4(dst, v0);
    atomicAdd4(dst + 4, v1);
}

// -------- layer1 epilogue + GEMM2 + per-node logits (layer2) ---------------
__global__ void k_node2(const float* __restrict__ W2,
                        const float* __restrict__ b1,
                        const float* __restrict__ att_s2,
                        const float* __restrict__ att_d2, int N) {
    int n = blockIdx.x * blockDim.x + threadIdx.x;
    if (n >= N) return;
    float acc[16];
#pragma unroll
    for (int c = 0; c < 16; c++) acc[c] = 0.f;
    const float* hrow = g_h + (size_t)n * 64;
#pragma unroll 4
    for (int j = 0; j < 64; j++) {
        float hj = hrow[j] + __ldg(b1 + j);
        const float* wrow = W2 + j * 16;
#pragma unroll
        for (int c = 0; c < 16; c++) acc[c] += hj * __ldg(wrow + c);
    }
    float sa = 0.f, sd = 0.f;
#pragma unroll
    for (int c = 0; c < 16; c++) {
        g_hl2[n * 16 + c] = acc[c];
        sa += acc[c] * __ldg(att_s2 + c);
        sd += acc[c] * __ldg(att_d2 + c);
    }
    g_as2[n] = sa;
    g_ad2[n] = sd;
}

// --------------------------- edge pass A (layer2) --------------------------
__global__ void k_edge2a(const int* __restrict__ ei, int E, int N) {
    int e = blockIdx.x * blockDim.x + threadIdx.x;
    int E2 = E + N;
    if (e >= E2) return;
    int s, d;
    if (e < E) { s = ei[e]; d = ei[E + e]; } else { s = d = e - E; }
    float w = __expf(leaky02(g_as2[s] + g_ad2[d]));
    atomicAdd(&g_den2[d], w);
}

// --------------------------- edge pass B (layer2) --------------------------
// one thread per (edge, quarter): 1 float4 gather, 1 float4 atomic
__global__ void k_edge2b(const int* __restrict__ ei, int E, int N) {
    int tid = blockIdx.x * blockDim.x + threadIdx.x;
    int E2 = E + N;
    int e = tid >> 2, q = tid & 3;
    if (e >= E2) return;
    int s, d;
    if (e < E) { s = ei[e]; d = ei[E + e]; } else { s = d = e - E; }
    float coef = __expf(leaky02(g_as2[s] + g_ad2[d])) / (g_den2[d] + 1e-16f);
    float4 v = *(const float4*)(g_hl2 + (size_t)s * 16 + q * 4);
    v.x *= coef; v.y *= coef; v.z *= coef; v.w *= coef;
    atomicAdd4(&g_o2[(size_t)d * 16 + q * 4], v);
}

// ------------------------ elu + log_softmax --------------------------------
__global__ void k_final(const float* __restrict__ b2, float* __restrict__ out,
                        int N) {
    int n = blockIdx.x * blockDim.x + threadIdx.x;
    if (n >= N) return;
    float v[16];
    float m = -1e30f;
#pragma unroll
    for (int c = 0; c < 16; c++) {
        float x = g_o2[n * 16 + c] + __ldg(b2 + c);
        x = (x > 0.f) ? x : (__expf(x) - 1.f);
        v[c] = x;
        m = fmaxf(m, x);
    }
    float ssum = 0.f;
#pragma unroll
    for (int c = 0; c < 16; c++) ssum += __expf(v[c] - m);
    float lse = m + __logf(ssum);
    float4* o4 = (float4*)(out + (size_t)n * 16);
#pragma unroll
    for (int q = 0; q < 4; q++) {
        o4[q] = make_float4(v[q * 4 + 0] - lse, v[q * 4 + 1] - lse,
                            v[q * 4 + 2] - lse, v[q * 4 + 3] - lse);
    }
}

// ---------------------------------------------------------------------------
extern "C" void kernel_launch(void* const* d_in, const int* in_sizes, int n_in,
                              void* d_out, int out_size) {
    const float* x      = (const float*)d_in[0];
    const int*   ei     = (const int*)d_in[1];
    const float* W1     = (const float*)d_in[2];
    const float* atts1  = (const float*)d_in[3];
    const float* attd1  = (const float*)d_in[4];
    const float* b1     = (const float*)d_in[5];
    const float* W2     = (const float*)d_in[6];
    const float* atts2  = (const float*)d_in[7];
    const float* attd2  = (const float*)d_in[8];
    const float* b2     = (const float*)d_in[9];
    float* out = (float*)d_out;

    const int N = in_sizes[0] / 512;
    const int E = in_sizes[1] / 2;
    const int E2 = E + N;

    k_zero<<<2048, 256>>>(N);
    k_gemm1<<<(N + 63) / 64, 256>>>(x, W1, N);
    k_node1<<<(N + 255) / 256, 256>>>(atts1, attd1, N);
    k_edge1a<<<(E2 + 255) / 256, 256>>>(ei, E, N);
    k_edge1b<<<(E2 * 8 + 255) / 256, 256>>>(ei, E, N);
    k_node2<<<(N + 255) / 256, 256>>>(W2, b1, atts2, attd2, N);
    k_edge2a<<<(E2 + 255) / 256, 256>>>(ei, E, N);
    k_edge2b<<<(E2 * 4 + 255) / 256, 256>>>(ei, E, N);
    k_final<<<(N + 255) / 256, 256>>>(b2, out, N);
}

// round 2
// speedup vs baseline: 1.1838x; 1.1838x over previous
#include <cuda_runtime.h>

// ---------------------------------------------------------------------------
// GATNet 2-layer GAT, N=50000, E=800000 (+N self loops), f32.
// CSR-by-dst rebuilt on device each call; aggregation = 1 register pass per
// layer (num = sum w*x, den = sum w, out = num/den), zero atomics on floats.
// ---------------------------------------------------------------------------

#define NMAX 50000
#define EMAX 800000

__device__ __align__(16) float g_xl [NMAX * 64];
__device__ __align__(16) float g_as1[NMAX * 8];
__device__ __align__(16) float g_ad1[NMAX * 8];
__device__ __align__(16) float g_h  [NMAX * 64];
__device__ __align__(16) float g_hl2[NMAX * 16];
__device__ float g_as2[NMAX];
__device__ float g_ad2[NMAX];

__device__ int g_cnt [NMAX];
__device__ int g_inc [NMAX];
__device__ int g_bsum[64];
__device__ int g_rptr[NMAX + 1];
__device__ int g_fill[NMAX];
__device__ int g_col [EMAX];

__device__ __forceinline__ float leaky02(float a) {
    return fmaxf(a, 0.2f * a);
}

// ----------------------------- CSR construction ----------------------------
__global__ void k_zero_cnt(int N) {
    int i = blockIdx.x * blockDim.x + threadIdx.x;
    if (i < N) g_cnt[i] = 0;
}

__global__ void k_hist(const int* __restrict__ ei, int E) {
    int e = blockIdx.x * blockDim.x + threadIdx.x;
    if (e < E) atomicAdd(&g_cnt[ei[E + e]], 1);
}

__global__ __launch_bounds__(1024) void k_scan1(int N) {
    __shared__ int sh[1024];
    int i = blockIdx.x * 1024 + threadIdx.x;
    int v = (i < N) ? g_cnt[i] : 0;
    sh[threadIdx.x] = v;
    __syncthreads();
#pragma unroll
    for (int off = 1; off < 1024; off <<= 1) {
        int t = (threadIdx.x >= off) ? sh[threadIdx.x - off] : 0;
        __syncthreads();
        sh[threadIdx.x] += t;
        __syncthreads();
    }
    if (i < N) g_inc[i] = sh[threadIdx.x];
    if (threadIdx.x == 1023) g_bsum[blockIdx.x] = sh[1023];
}

__global__ void k_scan2(int ntiles) {
    __shared__ int sh[64];
    int t = threadIdx.x;
    int v = (t < ntiles) ? g_bsum[t] : 0;
    sh[t] = v;
    __syncthreads();
#pragma unroll
    for (int off = 1; off < 64; off <<= 1) {
        int u = (t >= off) ? sh[t - off] : 0;
        __syncthreads();
        sh[t] += u;
        __syncthreads();
    }
    g_bsum[t] = sh[t] - v;   // exclusive
}

__global__ void k_scan3(int N, int E) {
    int i = blockIdx.x * blockDim.x + threadIdx.x;
    if (i < N) {
        int rp = g_inc[i] - g_cnt[i] + g_bsum[i >> 10];
        g_rptr[i] = rp;
        g_fill[i] = rp;
    }
    if (i == 0) g_rptr[N] = E;
}

__global__ void k_scatter(const int* __restrict__ ei, int E) {
    int e = blockIdx.x * blockDim.x + threadIdx.x;
    if (e >= E) return;
    int s = ei[e], d = ei[E + e];
    int pos = atomicAdd(&g_fill[d], 1);
    g_col[pos] = s;
}

// ------------------------------- GEMM1: xl = x @ W1 ------------------------
__global__ __launch_bounds__(256) void k_gemm1(const float* __restrict__ X,
                                               const float* __restrict__ W,
                                               int N) {
    __shared__ float sA[32][68];
    __shared__ float sB[32][64];
    const int block_m = blockIdx.x * 64;
    const int tid = threadIdx.x;
    const int tn = tid & 15, tm = tid >> 4;

    float acc[4][4];
#pragma unroll
    for (int i = 0; i < 4; i++)
#pragma unroll
        for (int j = 0; j < 4; j++) acc[i][j] = 0.f;

    const int ca = tid & 31, ra0 = tid >> 5;
    const int nb = tid & 63, kb0 = tid >> 6;

    for (int k0 = 0; k0 < 512; k0 += 32) {
#pragma unroll
        for (int p = 0; p < 8; p++) {
            int r = ra0 + p * 8;
            int gr = block_m + r;
            sA[ca][r] = (gr < N) ? X[(size_t)gr * 512 + (k0 + ca)] : 0.f;
        }
#pragma unroll
        for (int p = 0; p < 8; p++) {
            int kk = kb0 + p * 4;
            sB[kk][nb] = W[(size_t)(k0 + kk) * 64 + nb];
        }
        __syncthreads();
#pragma unroll
        for (int kk = 0; kk < 32; kk++) {
            float4 a = *(const float4*)&sA[kk][tm * 4];
            float4 b = *(const float4*)&sB[kk][tn * 4];
            acc[0][0] += a.x * b.x; acc[0][1] += a.x * b.y;
            acc[0][2] += a.x * b.z; acc[0][3] += a.x * b.w;
            acc[1][0] += a.y * b.x; acc[1][1] += a.y * b.y;
            acc[1][2] += a.y * b.z; acc[1][3] += a.y * b.w;
            acc[2][0] += a.z * b.x; acc[2][1] += a.z * b.y;
            acc[2][2] += a.z * b.z; acc[2][3] += a.z * b.w;
            acc[3][0] += a.w * b.x; acc[3][1] += a.w * b.y;
            acc[3][2] += a.w * b.z; acc[3][3] += a.w * b.w;
        }
        __syncthreads();
    }
#pragma unroll
    for (int i = 0; i < 4; i++) {
        int row = block_m + tm * 4 + i;
        if (row < N) {
            *(float4*)&g_xl[(size_t)row * 64 + tn * 4] =
                make_float4(acc[i][0], acc[i][1], acc[i][2], acc[i][3]);
        }
    }
}

// --------------------- per-node attention logits (layer1) ------------------
__global__ void k_node1(const float* __restrict__ att_s,
                        const float* __restrict__ att_d, int N) {
    int n = blockIdx.x * blockDim.x + threadIdx.x;
    if (n >= N) return;
    const float* xl = g_xl + (size_t)n * 64;
#pragma unroll
    for (int h = 0; h < 8; h++) {
        float s = 0.f, d = 0.f;
#pragma unroll
        for (int c = 0; c < 8; c++) {
            float v = xl[h * 8 + c];
            s += v * __ldg(att_s + h * 8 + c);
            d += v * __ldg(att_d + h * 8 + c);
        }
        g_as1[n * 8 + h] = s;
        g_ad1[n * 8 + h] = d;
    }
}

// ------------------- layer1 aggregation: warp per dst node ------------------
// lane l -> features {2l, 2l+1}, head h = l>>2.  No atomics.
__global__ __launch_bounds__(256) void k_agg1(int N) {
    int warp = (blockIdx.x * blockDim.x + threadIdx.x) >> 5;
    int lane = threadIdx.x & 31;
    if (warp >= N) return;
    const int d = warp;
    const int h = lane >> 2;
    const float ad = g_ad1[d * 8 + h];

    // self loop
    float w = __expf(leaky02(g_as1[d * 8 + h] + ad));
    float2 v = *(const float2*)&g_xl[(size_t)d * 64 + lane * 2];
    float nx = w * v.x, ny = w * v.y;
    float den = ((lane & 3) == 0) ? w : 0.f;

    const int e1 = g_rptr[d + 1];
#pragma unroll 4
    for (int e = g_rptr[d]; e < e1; e++) {
        int s = g_col[e];
        float we = __expf(leaky02(g_as1[s * 8 + h] + ad));
        float2 xs = *(const float2*)&g_xl[(size_t)s * 64 + lane * 2];
        nx += we * xs.x;
        ny += we * xs.y;
        if ((lane & 3) == 0) den += we;
    }
    float dfull = __shfl_sync(0xffffffffu, den, lane & ~3) + 1e-16f;
    float inv = 1.f / dfull;
    *(float2*)&g_h[(size_t)d * 64 + lane * 2] = make_float2(nx * inv, ny * inv);
}

// -------- layer1 bias + GEMM2 + per-node logits (layer2) -------------------
__global__ void k_node2(const float* __restrict__ W2,
                        const float* __restrict__ b1,
                        const float* __restrict__ att_s2,
                        const float* __restrict__ att_d2, int N) {
    int n = blockIdx.x * blockDim.x + threadIdx.x;
    if (n >= N) return;
    float acc[16];
#pragma unroll
    for (int c = 0; c < 16; c++) acc[c] = 0.f;
    const float* hrow = g_h + (size_t)n * 64;
#pragma unroll 4
    for (int j = 0; j < 64; j++) {
        float hj = hrow[j] + __ldg(b1 + j);
        const float* wrow = W2 + j * 16;
#pragma unroll
        for (int c = 0; c < 16; c++) acc[c] += hj * __ldg(wrow + c);
    }
    float sa = 0.f, sd = 0.f;
#pragma unroll
    for (int c = 0; c < 16; c++) {
        g_hl2[n * 16 + c] = acc[c];
        sa += acc[c] * __ldg(att_s2 + c);
        sd += acc[c] * __ldg(att_d2 + c);
    }
    g_as2[n] = sa;
    g_ad2[n] = sd;
}

// ------ layer2 aggregation + bias + elu + log_softmax (16 lanes/node) ------
__global__ __launch_bounds__(256) void k_agg2(const float* __restrict__ b2,
                                              float* __restrict__ out, int N) {
    int gid = (blockIdx.x * blockDim.x + threadIdx.x) >> 4;
    int c = threadIdx.x & 15;
    bool valid = gid < N;
    const int d = valid ? gid : 0;
    const float ad = g_ad2[d];

    float w = __expf(leaky02(g_as2[d] + ad));
    float num = w * g_hl2[(size_t)d * 16 + c];
    float den = w;

    const int e1 = g_rptr[d + 1];
#pragma unroll 4
    for (int e = g_rptr[d]; e < e1; e++) {
        int s = g_col[e];
        float we = __expf(leaky02(g_as2[s] + ad));
        num += we * g_hl2[(size_t)s * 16 + c];
        den += we;
    }
    float x = num / (den + 1e-16f) + __ldg(b2 + c);
    x = (x > 0.f) ? x : (__expf(x) - 1.f);

    float m = x;
#pragma unroll
    for (int off = 1; off < 16; off <<= 1)
        m = fmaxf(m, __shfl_xor_sync(0xffffffffu, m, off));
    float ssum = __expf(x - m);
#pragma unroll
    for (int off = 1; off < 16; off <<= 1)
        ssum += __shfl_xor_sync(0xffffffffu, ssum, off);
    if (valid) out[(size_t)d * 16 + c] = x - m - __logf(ssum);
}

// ---------------------------------------------------------------------------
extern "C" void kernel_launch(void* const* d_in, const int* in_sizes, int n_in,
                              void* d_out, int out_size) {
    const float* x     = (const float*)d_in[0];
    const int*   ei    = (const int*)d_in[1];
    const float* W1    = (const float*)d_in[2];
    const float* atts1 = (const float*)d_in[3];
    const float* attd1 = (const float*)d_in[4];
    const float* b1    = (const float*)d_in[5];
    const float* W2    = (const float*)d_in[6];
    const float* atts2 = (const float*)d_in[7];
    const float* attd2 = (const float*)d_in[8];
    const float* b2    = (const float*)d_in[9];
    float* out = (float*)d_out;

    const int N = in_sizes[0] / 512;
    const int E = in_sizes[1] / 2;
    const int ntiles = (N + 1023) >> 10;

    // CSR build (dst-sorted)
    k_zero_cnt<<<(N + 255) / 256, 256>>>(N);
    k_hist<<<(E + 255) / 256, 256>>>(ei, E);
    k_scan1<<<ntiles, 1024>>>(N);
    k_scan2<<<1, 64>>>(ntiles);
    k_scan3<<<(N + 255) / 256, 256>>>(N, E);
    k_scatter<<<(E + 255) / 256, 256>>>(ei, E);

    // layer 1
    k_gemm1<<<(N + 63) / 64, 256>>>(x, W1, N);
    k_node1<<<(N + 255) / 256, 256>>>(atts1, attd1, N);
    k_agg1<<<(N * 32 + 255) / 256, 256>>>(N);

    // layer 2 + epilogue
    k_node2<<<(N + 255) / 256, 256>>>(W2, b1, atts2, attd2, N);
    k_agg2<<<(N * 16 + 255) / 256, 256>>>(b2, out, N);
}

// round 4
// speedup vs baseline: 1.2911x; 1.0907x over previous
#include <cuda_runtime.h>
#include <cstdint>

// ---------------------------------------------------------------------------
// GATNet 2-layer GAT, N=50000, E=800000 (+self loops).
// GEMM1 = 3xTF32 tensor-core GEMM (error-compensated, ~fp32 accuracy) with
// fused attention logits. CSR-by-dst rebuilt per call; register aggregation.
// ---------------------------------------------------------------------------

#define NMAX 50000
#define EMAX 800000

__device__ __align__(16) float g_xl [NMAX * 64];
__device__ __align__(16) float g_as1[NMAX * 8];
__device__ __align__(16) float g_ad1[NMAX * 8];
__device__ __align__(16) float g_h  [NMAX * 64];
__device__ __align__(16) float g_hl2[NMAX * 16];
__device__ float g_as2[NMAX];
__device__ float g_ad2[NMAX];

__device__ int g_cnt [NMAX];
__device__ int g_inc [NMAX];
__device__ int g_bsum[64];
__device__ int g_rptr[NMAX + 1];
__device__ int g_fill[NMAX];
__device__ int g_col [EMAX];

__device__ __forceinline__ float leaky02(float a) { return fmaxf(a, 0.2f * a); }

__device__ __forceinline__ float tf32r(float x) {
    uint32_t u;
    asm("cvt.rna.tf32.f32 %0, %1;" : "=r"(u) : "f"(x));
    return __uint_as_float(u);
}

__device__ __forceinline__ void mma_tf32(float4& c, uint32_t a0, uint32_t a1,
                                         uint32_t a2, uint32_t a3,
                                         uint32_t b0, uint32_t b1) {
    asm volatile(
        "mma.sync.aligned.m16n8k8.row.col.f32.tf32.tf32.f32 "
        "{%0,%1,%2,%3}, {%4,%5,%6,%7}, {%8,%9}, {%0,%1,%2,%3};\n"
        : "+f"(c.x), "+f"(c.y), "+f"(c.z), "+f"(c.w)
        : "r"(a0), "r"(a1), "r"(a2), "r"(a3), "r"(b0), "r"(b1));
}

// ----------------------------- CSR construction ----------------------------
__global__ void k_zero_cnt(int N) {
    int i = blockIdx.x * blockDim.x + threadIdx.x;
    if (i < N) g_cnt[i] = 0;
}

__global__ void k_hist(const int* __restrict__ ei, int E) {
    int e = blockIdx.x * blockDim.x + threadIdx.x;
    if (e < E) atomicAdd(&g_cnt[ei[E + e]], 1);
}

__global__ __launch_bounds__(1024) void k_scan1(int N) {
    __shared__ int sh[1024];
    int i = blockIdx.x * 1024 + threadIdx.x;
    int v = (i < N) ? g_cnt[i] : 0;
    sh[threadIdx.x] = v;
    __syncthreads();
#pragma unroll
    for (int off = 1; off < 1024; off <<= 1) {
        int t = (threadIdx.x >= off) ? sh[threadIdx.x - off] : 0;
        __syncthreads();
        sh[threadIdx.x] += t;
        __syncthreads();
    }
    if (i < N) g_inc[i] = sh[threadIdx.x];
    if (threadIdx.x == 1023) g_bsum[blockIdx.x] = sh[1023];
}

// per-block redundant scan of the <=64 block sums (no divergent barriers)
__global__ void k_scan3(int N, int E, int ntiles) {
    __shared__ int sh[64];
    int t = threadIdx.x;
    if (t < 64) sh[t] = (t < ntiles) ? g_bsum[t] : 0;
    __syncthreads();
#pragma unroll
    for (int off = 1; off < 64; off <<= 1) {
        int u = 0;
        if (t < 64 && t >= off) u = sh[t - off];
        __syncthreads();
        if (t < 64) sh[t] += u;
        __syncthreads();
    }
    int i = blockIdx.x * blockDim.x + t;
    if (i < N) {
        int blk = i >> 10;
        int excl = (blk == 0) ? 0 : sh[blk - 1];
        int rp = g_inc[i] - g_cnt[i] + excl;
        g_rptr[i] = rp;
        g_fill[i] = rp;
    }
    if (i == 0) g_rptr[N] = E;
}

__global__ void k_scatter(const int* __restrict__ ei, int E) {
    int e = blockIdx.x * blockDim.x + threadIdx.x;
    if (e >= E) return;
    int s = ei[e], d = ei[E + e];
    int pos = atomicAdd(&g_fill[d], 1);
    g_col[pos] = s;
}

// --------------- GEMM1 (3xTF32 MMA) + fused node1 logits -------------------
// xl = X @ W1. Block tile 64x64, 8 warps (wm 0..3 over M16, wn 0..1 over N32).
__global__ __launch_bounds__(256) void k_gemm1(const float* __restrict__ X,
                                               const float* __restrict__ W,
                                               const float* __restrict__ att_s,
                                               const float* __restrict__ att_d,
                                               int N) {
    __shared__ float sAh[64][36], sAl[64][36];
    __shared__ float sBh[32][68], sBl[32][68];
    const int tid  = threadIdx.x;
    const int bm   = blockIdx.x * 64;
    const int warp = tid >> 5, lane = tid & 31;
    const int wm   = warp >> 1, wn = warp & 1;
    const int g    = lane >> 2, tig = lane & 3;

    // global load mapping: A 64x32 tile (8 floats/thread), B 32x64 (8/thread)
    const int ar = tid >> 2, ah = (tid & 3) * 8;
    const int bk = tid >> 3, bq = (tid & 7) * 8;

    int axr = bm + ar;
    if (axr >= N) axr = N - 1;  // clamp; stores guarded
    const float4* Xr = (const float4*)(X + (size_t)axr * 512);

    float4 acc[4];
#pragma unroll
    for (int i = 0; i < 4; i++) acc[i] = make_float4(0.f, 0.f, 0.f, 0.f);

    float4 ra[2], rb[2];
#pragma unroll
    for (int i = 0; i < 2; i++) ra[i] = Xr[(ah >> 2) + i];
#pragma unroll
    for (int i = 0; i < 2; i++)
        rb[i] = ((const float4*)(W + (size_t)bk * 64 + bq))[i];

    for (int ks = 0; ks < 16; ks++) {
#pragma unroll
        for (int i = 0; i < 2; i++) {
            float4 h4 = make_float4(tf32r(ra[i].x), tf32r(ra[i].y),
                                    tf32r(ra[i].z), tf32r(ra[i].w));
            float4 l4 = make_float4(tf32r(ra[i].x - h4.x), tf32r(ra[i].y - h4.y),
                                    tf32r(ra[i].z - h4.z), tf32r(ra[i].w - h4.w));
            *(float4*)&sAh[ar][ah + i * 4] = h4;
            *(float4*)&sAl[ar][ah + i * 4] = l4;
        }
#pragma unroll
        for (int i = 0; i < 2; i++) {
            float4 h4 = make_float4(tf32r(rb[i].x), tf32r(rb[i].y),
                                    tf32r(rb[i].z), tf32r(rb[i].w));
            float4 l4 = make_float4(tf32r(rb[i].x - h4.x), tf32r(rb[i].y - h4.y),
                                    tf32r(rb[i].z - h4.z), tf32r(rb[i].w - h4.w));
            *(float4*)&sBh[bk][bq + i * 4] = h4;
            *(float4*)&sBl[bk][bq + i * 4] = l4;
        }
        __syncthreads();
        if (ks < 15) {
            int k0 = (ks + 1) * 32;
#pragma unroll
            for (int i = 0; i < 2; i++) ra[i] = Xr[((k0 + ah) >> 2) + i];
#pragma unroll
            for (int i = 0; i < 2; i++)
                rb[i] = ((const float4*)(W + (size_t)(k0 + bk) * 64 + bq))[i];
        }
#pragma unroll
        for (int ksub = 0; ksub < 4; ksub++) {
            const int kc = ksub * 8;
            const int r0 = wm * 16 + g, r1 = r0 + 8;
            uint32_t ah0 = __float_as_uint(sAh[r0][kc + tig]);
            uint32_t ah1 = __float_as_uint(sAh[r1][kc + tig]);
            uint32_t ah2 = __float_as_uint(sAh[r0][kc + tig + 4]);
            uint32_t ah3 = __float_as_uint(sAh[r1][kc + tig + 4]);
            uint32_t al0 = __float_as_uint(sAl[r0][kc + tig]);
            uint32_t al1 = __float_as_uint(sAl[r1][kc + tig]);
            uint32_t al2 = __float_as_uint(sAl[r0][kc + tig + 4]);
            uint32_t al3 = __float_as_uint(sAl[r1][kc + tig + 4]);
#pragma unroll
            for (int nt = 0; nt < 4; nt++) {
                const int nc = wn * 32 + nt * 8 + g;
                uint32_t bh0 = __float_as_uint(sBh[kc + tig][nc]);
                uint32_t bh1 = __float_as_uint(sBh[kc + tig + 4][nc]);
                uint32_t bl0 = __float_as_uint(sBl[kc + tig][nc]);
                uint32_t bl1 = __float_as_uint(sBl[kc + tig + 4][nc]);
                mma_tf32(acc[nt], al0, al1, al2, al3, bh0, bh1);
                mma_tf32(acc[nt], ah0, ah1, ah2, ah3, bl0, bl1);
                mma_tf32(acc[nt], ah0, ah1, ah2, ah3, bh0, bh1);
            }
        }
        __syncthreads();
    }

    const int row0 = bm + wm * 16 + g;
    const int row1 = row0 + 8;

    float s0a[4], s1a[4], d0a[4], d1a[4];
#pragma unroll
    for (int nt = 0; nt < 4; nt++) {
        const int h = wn * 4 + nt;           // head owned by this (warp, nt)
        const int col = h * 8 + tig * 2;
        if (row0 < N)
            *(float2*)&g_xl[(size_t)row0 * 64 + col] =
                make_float2(acc[nt].x, acc[nt].y);
        if (row1 < N)
            *(float2*)&g_xl[(size_t)row1 * 64 + col] =
                make_float2(acc[nt].z, acc[nt].w);

        float2 asv = make_float2(__ldg(att_s + h * 8 + 2 * tig),
                                 __ldg(att_s + h * 8 + 2 * tig + 1));
        float2 adv = make_float2(__ldg(att_d + h * 8 + 2 * tig),
                                 __ldg(att_d + h * 8 + 2 * tig + 1));
        float s0 = acc[nt].x * asv.x + acc[nt].y * asv.y;
        float s1 = acc[nt].z * asv.x + acc[nt].w * asv.y;
        float d0 = acc[nt].x * adv.x + acc[nt].y * adv.y;
        float d1 = acc[nt].z * adv.x + acc[nt].w * adv.y;
#pragma unroll
        for (int off = 1; off < 4; off <<= 1) {
            s0 += __shfl_xor_sync(0xffffffffu, s0, off);
            s1 += __shfl_xor_sync(0xffffffffu, s1, off);
            d0 += __shfl_xor_sync(0xffffffffu, d0, off);
            d1 += __shfl_xor_sync(0xffffffffu, d1, off);
        }
        s0a[nt] = s0; s1a[nt] = s1; d0a[nt] = d0; d1a[nt] = d1;
    }
    if (tig == 0) {
        if (row0 < N) {
            *(float4*)&g_as1[row0 * 8 + wn * 4] =
                make_float4(s0a[0], s0a[1], s0a[2], s0a[3]);
            *(float4*)&g_ad1[row0 * 8 + wn * 4] =
                make_float4(d0a[0], d0a[1], d0a[2], d0a[3]);
        }
        if (row1 < N) {
            *(float4*)&g_as1[row1 * 8 + wn * 4] =
                make_float4(s1a[0], s1a[1], s1a[2], s1a[3]);
            *(float4*)&g_ad1[row1 * 8 + wn * 4] =
                make_float4(d1a[0], d1a[1], d1a[2], d1a[3]);
        }
    }
}

// ------------------- layer1 aggregation: warp per dst node ------------------
__global__ __launch_bounds__(256) void k_agg1(int N) {
    int warp = (blockIdx.x * blockDim.x + threadIdx.x) >> 5;
    int lane = threadIdx.x & 31;
    if (warp >= N) return;
    const int d = warp;
    const int h = lane >> 2;
    const float ad = g_ad1[d * 8 + h];

    float w = __expf(leaky02(g_as1[d * 8 + h] + ad));
    float2 v = *(const float2*)&g_xl[(size_t)d * 64 + lane * 2];
    float nx = w * v.x, ny = w * v.y;
    float den = ((lane & 3) == 0) ? w : 0.f;

    const int e1 = g_rptr[d + 1];
#pragma unroll 4
    for (int e = g_rptr[d]; e < e1; e++) {
        int s = g_col[e];
        float we = __expf(leaky02(g_as1[s * 8 + h] + ad));
        float2 xs = *(const float2*)&g_xl[(size_t)s * 64 + lane * 2];
        nx += we * xs.x;
        ny += we * xs.y;
        if ((lane & 3) == 0) den += we;
    }
    float dfull = __shfl_sync(0xffffffffu, den, lane & ~3) + 1e-16f;
    float inv = 1.f / dfull;
    *(float2*)&g_h[(size_t)d * 64 + lane * 2] = make_float2(nx * inv, ny * inv);
}

// -------- layer1 bias + GEMM2 + per-node logits (layer2) -------------------
__global__ void k_node2(const float* __restrict__ W2,
                        const float* __restrict__ b1,
                        const float* __restrict__ att_s2,
                        const float* __restrict__ att_d2, int N) {
    int n = blockIdx.x * blockDim.x + threadIdx.x;
    if (n >= N) return;
    float acc[16];
#pragma unroll
    for (int c = 0; c < 16; c++) acc[c] = 0.f;
    const float* hrow = g_h + (size_t)n * 64;
#pragma unroll 4
    for (int j = 0; j < 64; j++) {
        float hj = hrow[j] + __ldg(b1 + j);
        const float* wrow = W2 + j * 16;
#pragma unroll
        for (int c = 0; c < 16; c++) acc[c] += hj * __ldg(wrow + c);
    }
    float sa = 0.f, sd = 0.f;
#pragma unroll
    for (int c = 0; c < 16; c++) {
        g_hl2[n * 16 + c] = acc[c];
        sa += acc[c] * __ldg(att_s2 + c);
        sd += acc[c] * __ldg(att_d2 + c);
    }
    g_as2[n] = sa;
    g_ad2[n] = sd;
}

// ------ layer2 aggregation + bias + elu + log_softmax (16 lanes/node) ------
__global__ __launch_bounds__(256) void k_agg2(const float* __restrict__ b2,
                                              float* __restrict__ out, int N) {
    int gid = (blockIdx.x * blockDim.x + threadIdx.x) >> 4;
    int c = threadIdx.x & 15;
    bool valid = gid < N;
    const int d = valid ? gid : 0;
    const float ad = g_ad2[d];

    float w = __expf(leaky02(g_as2[d] + ad));
    float num = w * g_hl2[(size_t)d * 16 + c];
    float den = w;

    const int e1 = g_rptr[d + 1];
#pragma unroll 4
    for (int e = g_rptr[d]; e < e1; e++) {
        int s = g_col[e];
        float we = __expf(leaky02(g_as2[s] + ad));
        num += we * g_hl2[(size_t)s * 16 + c];
        den += we;
    }
    float x = num / (den + 1e-16f) + __ldg(b2 + c);
    x = (x > 0.f) ? x : (__expf(x) - 1.f);

    float m = x;
#pragma unroll
    for (int off = 1; off < 16; off <<= 1)
        m = fmaxf(m, __shfl_xor_sync(0xffffffffu, m, off));
    float ssum = __expf(x - m);
#pragma unroll
    for (int off = 1; off < 16; off <<= 1)
        ssum += __shfl_xor_sync(0xffffffffu, ssum, off);
    if (valid) out[(size_t)d * 16 + c] = x - m - __logf(ssum);
}

// ---------------------------------------------------------------------------
extern "C" void kernel_launch(void* const* d_in, const int* in_sizes, int n_in,
                              void* d_out, int out_size) {
    const float* x     = (const float*)d_in[0];
    const int*   ei    = (const int*)d_in[1];
    const float* W1    = (const float*)d_in[2];
    const float* atts1 = (const float*)d_in[3];
    const float* attd1 = (const float*)d_in[4];
    const float* b1    = (const float*)d_in[5];
    const float* W2    = (const float*)d_in[6];
    const float* atts2 = (const float*)d_in[7];
    const float* attd2 = (const float*)d_in[8];
    const float* b2    = (const float*)d_in[9];
    float* out = (float*)d_out;

    const int N = in_sizes[0] / 512;
    const int E = in_sizes[1] / 2;
    const int ntiles = (N + 1023) >> 10;

    // CSR build (dst-sorted)
    k_zero_cnt<<<(N + 255) / 256, 256>>>(N);
    k_hist<<<(E + 255) / 256, 256>>>(ei, E);
    k_scan1<<<ntiles, 1024>>>(N);
    k_scan3<<<(N + 255) / 256, 256>>>(N, E, ntiles);
    k_scatter<<<(E + 255) / 256, 256>>>(ei, E);

    // layer 1
    k_gemm1<<<(N + 63) / 64, 256>>>(x, W1, atts1, attd1, N);
    k_agg1<<<(N * 32 + 255) / 256, 256>>>(N);

    // layer 2 + epilogue
    k_node2<<<(N + 255) / 256, 256>>>(W2, b1, atts2, attd2, N);
    k_agg2<<<(N * 16 + 255) / 256, 256>>>(b2, out, N);
}

// round 5
// speedup vs baseline: 1.4627x; 1.1329x over previous
#include <cuda_runtime.h>
#include <cstdint>

// ---------------------------------------------------------------------------
// GATNet 2-layer GAT, N=50000, E=800000 (+self loops).
// GEMM1 = 3xTF32 tensor-core (128x64 tile, dynamic smem, conflict-free frags)
// with fused attention logits. CSR-by-dst per call (shuffle scans, no zero
// launch); register aggregation, no float atomics.
// ---------------------------------------------------------------------------

#define NMAX 50000
#define EMAX 800000

__device__ __align__(16) float g_xl [NMAX * 64];
__device__ __align__(16) float g_as1[NMAX * 8];
__device__ __align__(16) float g_ad1[NMAX * 8];
__device__ __align__(16) float g_h  [NMAX * 64];
__device__ __align__(16) float g_hl2[NMAX * 16];
__device__ float g_as2[NMAX];
__device__ float g_ad2[NMAX];

__device__ int g_cnt [NMAX];   // zero at module load; re-zeroed by k_scatter
__device__ int g_inc [NMAX];
__device__ int g_bsum[64];
__device__ int g_rptr[NMAX + 1];
__device__ int g_fill[NMAX];
__device__ int g_col [EMAX];

__device__ __forceinline__ float leaky02(float a) { return fmaxf(a, 0.2f * a); }

__device__ __forceinline__ float tf32r(float x) {
    uint32_t u;
    asm("cvt.rna.tf32.f32 %0, %1;" : "=r"(u) : "f"(x));
    return __uint_as_float(u);
}

__device__ __forceinline__ void mma_tf32(float4& c, uint32_t a0, uint32_t a1,
                                         uint32_t a2, uint32_t a3,
                                         uint32_t b0, uint32_t b1) {
    asm volatile(
        "mma.sync.aligned.m16n8k8.row.col.f32.tf32.tf32.f32 "
        "{%0,%1,%2,%3}, {%4,%5,%6,%7}, {%8,%9}, {%0,%1,%2,%3};\n"
        : "+f"(c.x), "+f"(c.y), "+f"(c.z), "+f"(c.w)
        : "r"(a0), "r"(a1), "r"(a2), "r"(a3), "r"(b0), "r"(b1));
}

// ----------------------------- CSR construction ----------------------------
__global__ void k_hist(const int* __restrict__ ei, int E) {
    int e = blockIdx.x * blockDim.x + threadIdx.x;
    if (e < E) atomicAdd(&g_cnt[ei[E + e]], 1);
}

__global__ __launch_bounds__(1024) void k_scan1(int N) {
    __shared__ int sw[32];
    int t = threadIdx.x, i = blockIdx.x * 1024 + t;
    int lane = t & 31, wid = t >> 5;
    int s = (i < N) ? g_cnt[i] : 0;
#pragma unroll
    for (int o = 1; o < 32; o <<= 1) {
        int u = __shfl_up_sync(0xffffffffu, s, o);
        if (lane >= o) s += u;
    }
    if (lane == 31) sw[wid] = s;
    __syncthreads();
    if (wid == 0) {
        int ws = sw[lane];
#pragma unroll
        for (int o = 1; o < 32; o <<= 1) {
            int u = __shfl_up_sync(0xffffffffu, ws, o);
            if (lane >= o) ws += u;
        }
        sw[lane] = ws;
    }
    __syncthreads();
    int incl = s + (wid ? sw[wid - 1] : 0);
    if (i < N) g_inc[i] = incl;
    if (t == 1023) g_bsum[blockIdx.x] = incl;
}

// rptr = exclusive global offset; per-block single-warp scan of block sums
__global__ void k_scan3(int N, int E, int ntiles) {
    __shared__ int sh[64];
    int t = threadIdx.x;
    if (t < 32) {
        int a = (t < ntiles) ? g_bsum[t] : 0;
        int b = (t + 32 < ntiles) ? g_bsum[t + 32] : 0;
#pragma unroll
        for (int o = 1; o < 32; o <<= 1) {
            int u = __shfl_up_sync(0xffffffffu, a, o);
            if (t >= o) a += u;
        }
        int tot = __shfl_sync(0xffffffffu, a, 31);
#pragma unroll
        for (int o = 1; o < 32; o <<= 1) {
            int u = __shfl_up_sync(0xffffffffu, b, o);
            if (t >= o) b += u;
        }
        sh[t] = a;
        sh[t + 32] = b + tot;
    }
    __syncthreads();
    int i = blockIdx.x * blockDim.x + t;
    if (i < N) {
        int blk = i >> 10;
        int excl = blk ? sh[blk - 1] : 0;
        int rp = g_inc[i] - g_cnt[i] + excl;
        g_rptr[i] = rp;
        g_fill[i] = rp;
    }
    if (i == 0) g_rptr[N] = E;
}

__global__ void k_scatter(const int* __restrict__ ei, int E, int N) {
    int e = blockIdx.x * blockDim.x + threadIdx.x;
    if (e < N) g_cnt[e] = 0;   // reset for the next call (cnt dead after scan3)
    if (e >= E) return;
    int s = ei[e], d = ei[E + e];
    int pos = atomicAdd(&g_fill[d], 1);
    g_col[pos] = s;
}

// --------------- GEMM1 (3xTF32 MMA) + fused node1 logits -------------------
// xl = X @ W1, block tile 128x64, 8 warps = 4(M) x 2(N), warp tile 32x32.
#define G1_SMEM_BYTES (2 * 128 * 36 * 4 + 2 * 32 * 72 * 4)  // 55296

__global__ __launch_bounds__(256) void k_gemm1(const float* __restrict__ X,
                                               const float* __restrict__ W,
                                               const float* __restrict__ att_s,
                                               const float* __restrict__ att_d,
                                               int N) {
    extern __shared__ float smem[];
    float (*sAh)[36] = (float(*)[36])(smem);
    float (*sAl)[36] = (float(*)[36])(smem + 128 * 36);
    float (*sBh)[72] = (float(*)[72])(smem + 2 * 128 * 36);
    float (*sBl)[72] = (float(*)[72])(smem + 2 * 128 * 36 + 32 * 72);

    const int tid  = threadIdx.x;
    const int bm   = blockIdx.x * 128;
    const int warp = tid >> 5, lane = tid & 31;
    const int wm   = warp >> 1, wn = warp & 1;
    const int g    = lane >> 2, tig = lane & 3;

    // global loaders: A 128x32 (16 floats/thr), B 32x64 (8 floats/thr)
    const int ar = tid >> 1, ah = (tid & 1) * 16;
    const int bk = tid >> 3, bq = (tid & 7) * 8;

    int axr = bm + ar;
    if (axr >= N) axr = N - 1;  // clamp; stores guarded
    const float4* Xr = (const float4*)(X + (size_t)axr * 512);

    float4 acc[2][4];
#pragma unroll
    for (int i = 0; i < 2; i++)
#pragma unroll
        for (int j = 0; j < 4; j++) acc[i][j] = make_float4(0.f, 0.f, 0.f, 0.f);

    float4 ra[4], rb[2];
#pragma unroll
    for (int i = 0; i < 4; i++) ra[i] = Xr[(ah >> 2) + i];
#pragma unroll
    for (int i = 0; i < 2; i++)
        rb[i] = ((const float4*)(W + (size_t)bk * 64 + bq))[i];

    for (int ks = 0; ks < 16; ks++) {
#pragma unroll
        for (int i = 0; i < 4; i++) {
            float4 h4 = make_float4(tf32r(ra[i].x), tf32r(ra[i].y),
                                    tf32r(ra[i].z), tf32r(ra[i].w));
            float4 l4 = make_float4(tf32r(ra[i].x - h4.x), tf32r(ra[i].y - h4.y),
                                    tf32r(ra[i].z - h4.z), tf32r(ra[i].w - h4.w));
            *(float4*)&sAh[ar][ah + i * 4] = h4;
            *(float4*)&sAl[ar][ah + i * 4] = l4;
        }
#pragma unroll
        for (int i = 0; i < 2; i++) {
            float4 h4 = make_float4(tf32r(rb[i].x), tf32r(rb[i].y),
                                    tf32r(rb[i].z), tf32r(rb[i].w));
            float4 l4 = make_float4(tf32r(rb[i].x - h4.x), tf32r(rb[i].y - h4.y),
                                    tf32r(rb[i].z - h4.z), tf32r(rb[i].w - h4.w));
            *(float4*)&sBh[bk][bq + i * 4] = h4;
            *(float4*)&sBl[bk][bq + i * 4] = l4;
        }
        __syncthreads();
        if (ks < 15) {
            int k0 = (ks + 1) * 32;
#pragma unroll
            for (int i = 0; i < 4; i++) ra[i] = Xr[((k0 + ah) >> 2) + i];
#pragma unroll
            for (int i = 0; i < 2; i++)
                rb[i] = ((const float4*)(W + (size_t)(k0 + bk) * 64 + bq))[i];
        }
#pragma unroll
        for (int ksub = 0; ksub < 4; ksub++) {
            const int kc = ksub * 8;
            uint32_t Ah[2][4], Al[2][4];
#pragma unroll
            for (int mt = 0; mt < 2; mt++) {
                const int r0 = wm * 32 + mt * 16 + g, r1 = r0 + 8;
                Ah[mt][0] = __float_as_uint(sAh[r0][kc + tig]);
                Ah[mt][1] = __float_as_uint(sAh[r1][kc + tig]);
                Ah[mt][2] = __float_as_uint(sAh[r0][kc + tig + 4]);
                Ah[mt][3] = __float_as_uint(sAh[r1][kc + tig + 4]);
                Al[mt][0] = __float_as_uint(sAl[r0][kc + tig]);
                Al[mt][1] = __float_as_uint(sAl[r1][kc + tig]);
                Al[mt][2] = __float_as_uint(sAl[r0][kc + tig + 4]);
                Al[mt][3] = __float_as_uint(sAl[r1][kc + tig + 4]);
            }
#pragma unroll
            for (int nt = 0; nt < 4; nt++) {
                const int nc = wn * 32 + nt * 8 + g;
                uint32_t bh0 = __float_as_uint(sBh[kc + tig][nc]);
                uint32_t bh1 = __float_as_uint(sBh[kc + tig + 4][nc]);
                uint32_t bl0 = __float_as_uint(sBl[kc + tig][nc]);
                uint32_t bl1 = __float_as_uint(sBl[kc + tig + 4][nc]);
#pragma unroll
                for (int mt = 0; mt < 2; mt++) {
                    mma_tf32(acc[mt][nt], Al[mt][0], Al[mt][1], Al[mt][2],
                             Al[mt][3], bh0, bh1);
                    mma_tf32(acc[mt][nt], Ah[mt][0], Ah[mt][1], Ah[mt][2],
                             Ah[mt][3], bl0, bl1);
                    mma_tf32(acc[mt][nt], Ah[mt][0], Ah[mt][1], Ah[mt][2],
                             Ah[mt][3], bh0, bh1);
                }
            }
        }
        __syncthreads();
    }

#pragma unroll
    for (int mt = 0; mt < 2; mt++) {
        const int row0 = bm + wm * 32 + mt * 16 + g;
        const int row1 = row0 + 8;
        float s0a[4], s1a[4], d0a[4], d1a[4];
#pragma unroll
        for (int nt = 0; nt < 4; nt++) {
            const int h = wn * 4 + nt;
            const int col = h * 8 + tig * 2;
            float4 a = acc[mt][nt];
            if (row0 < N)
                *(float2*)&g_xl[(size_t)row0 * 64 + col] = make_float2(a.x, a.y);
            if (row1 < N)
                *(float2*)&g_xl[(size_t)row1 * 64 + col] = make_float2(a.z, a.w);

            float2 asv = make_float2(__ldg(att_s + h * 8 + 2 * tig),
                                     __ldg(att_s + h * 8 + 2 * tig + 1));
            float2 adv = make_float2(__ldg(att_d + h * 8 + 2 * tig),
                                     __ldg(att_d + h * 8 + 2 * tig + 1));
            float s0 = a.x * asv.x + a.y * asv.y;
            float s1 = a.z * asv.x + a.w * asv.y;
            float d0 = a.x * adv.x + a.y * adv.y;
            float d1 = a.z * adv.x + a.w * adv.y;
#pragma unroll
            for (int off = 1; off < 4; off <<= 1) {
                s0 += __shfl_xor_sync(0xffffffffu, s0, off);
                s1 += __shfl_xor_sync(0xffffffffu, s1, off);
                d0 += __shfl_xor_sync(0xffffffffu, d0, off);
                d1 += __shfl_xor_sync(0xffffffffu, d1, off);
            }
            s0a[nt] = s0; s1a[nt] = s1; d0a[nt] = d0; d1a[nt] = d1;
        }
        if (tig == 0) {
            if (row0 < N) {
                *(float4*)&g_as1[row0 * 8 + wn * 4] =
                    make_float4(s0a[0], s0a[1], s0a[2], s0a[3]);
                *(float4*)&g_ad1[row0 * 8 + wn * 4] =
                    make_float4(d0a[0], d0a[1], d0a[2], d0a[3]);
            }
            if (row1 < N) {
                *(float4*)&g_as1[row1 * 8 + wn * 4] =
                    make_float4(s1a[0], s1a[1], s1a[2], s1a[3]);
                *(float4*)&g_ad1[row1 * 8 + wn * 4] =
                    make_float4(d1a[0], d1a[1], d1a[2], d1a[3]);
            }
        }
    }
}

// ------------------- layer1 aggregation: warp per dst node ------------------
__global__ __launch_bounds__(256) void k_agg1(int N) {
    int warp = (blockIdx.x * blockDim.x + threadIdx.x) >> 5;
    int lane = threadIdx.x & 31;
    if (warp >= N) return;
    const int d = warp;
    const int h = lane >> 2;
    const float ad = g_ad1[d * 8 + h];

    float w = __expf(leaky02(g_as1[d * 8 + h] + ad));
    float2 v = *(const float2*)&g_xl[(size_t)d * 64 + lane * 2];
    float nx = w * v.x, ny = w * v.y;
    float den = ((lane & 3) == 0) ? w : 0.f;

    const int e1 = g_rptr[d + 1];
#pragma unroll 4
    for (int e = g_rptr[d]; e < e1; e++) {
        int s = g_col[e];
        float we = __expf(leaky02(g_as1[s * 8 + h] + ad));
        float2 xs = *(const float2*)&g_xl[(size_t)s * 64 + lane * 2];
        nx += we * xs.x;
        ny += we * xs.y;
        if ((lane & 3) == 0) den += we;
    }
    float dfull = __shfl_sync(0xffffffffu, den, lane & ~3) + 1e-16f;
    float inv = 1.f / dfull;
    *(float2*)&g_h[(size_t)d * 64 + lane * 2] = make_float2(nx * inv, ny * inv);
}

// -------- layer1 bias + GEMM2 + per-node logits (layer2) -------------------
__global__ void k_node2(const float* __restrict__ W2,
                        const float* __restrict__ b1,
                        const float* __restrict__ att_s2,
                        const float* __restrict__ att_d2, int N) {
    int n = blockIdx.x * blockDim.x + threadIdx.x;
    if (n >= N) return;
    float acc[16];
#pragma unroll
    for (int c = 0; c < 16; c++) acc[c] = 0.f;
    const float* hrow = g_h + (size_t)n * 64;
#pragma unroll 4
    for (int j = 0; j < 64; j++) {
        float hj = hrow[j] + __ldg(b1 + j);
        const float* wrow = W2 + j * 16;
#pragma unroll
        for (int c = 0; c < 16; c++) acc[c] += hj * __ldg(wrow + c);
    }
    float sa = 0.f, sd = 0.f;
#pragma unroll
    for (int c = 0; c < 16; c++) {
        g_hl2[n * 16 + c] = acc[c];
        sa += acc[c] * __ldg(att_s2 + c);
        sd += acc[c] * __ldg(att_d2 + c);
    }
    g_as2[n] = sa;
    g_ad2[n] = sd;
}

// ------ layer2 aggregation + bias + elu + log_softmax (16 lanes/node) ------
__global__ __launch_bounds__(256) void k_agg2(const float* __restrict__ b2,
                                              float* __restrict__ out, int N) {
    int gid = (blockIdx.x * blockDim.x + threadIdx.x) >> 4;
    int c = threadIdx.x & 15;
    bool valid = gid < N;
    const int d = valid ? gid : 0;
    const float ad = g_ad2[d];

    float w = __expf(leaky02(g_as2[d] + ad));
    float num = w * g_hl2[(size_t)d * 16 + c];
    float den = w;

    const int e1 = g_rptr[d + 1];
#pragma unroll 4
    for (int e = g_rptr[d]; e < e1; e++) {
        int s = g_col[e];
        float we = __expf(leaky02(g_as2[s] + ad));
        num += we * g_hl2[(size_t)s * 16 + c];
        den += we;
    }
    float x = num / (den + 1e-16f) + __ldg(b2 + c);
    x = (x > 0.f) ? x : (__expf(x) - 1.f);

    float m = x;
#pragma unroll
    for (int off = 1; off < 16; off <<= 1)
        m = fmaxf(m, __shfl_xor_sync(0xffffffffu, m, off));
    float ssum = __expf(x - m);
#pragma unroll
    for (int off = 1; off < 16; off <<= 1)
        ssum += __shfl_xor_sync(0xffffffffu, ssum, off);
    if (valid) out[(size_t)d * 16 + c] = x - m - __logf(ssum);
}

// ---------------------------------------------------------------------------
extern "C" void kernel_launch(void* const* d_in, const int* in_sizes, int n_in,
                              void* d_out, int out_size) {
    const float* x     = (const float*)d_in[0];
    const int*   ei    = (const int*)d_in[1];
    const float* W1    = (const float*)d_in[2];
    const float* atts1 = (const float*)d_in[3];
    const float* attd1 = (const float*)d_in[4];
    const float* b1    = (const float*)d_in[5];
    const float* W2    = (const float*)d_in[6];
    const float* atts2 = (const float*)d_in[7];
    const float* attd2 = (const float*)d_in[8];
    const float* b2    = (const float*)d_in[9];
    float* out = (float*)d_out;

    const int N = in_sizes[0] / 512;
    const int E = in_sizes[1] / 2;
    const int ntiles = (N + 1023) >> 10;

    static bool attr_set = false;
    if (!attr_set) {
        cudaFuncSetAttribute(k_gemm1, cudaFuncAttributeMaxDynamicSharedMemorySize,
                             G1_SMEM_BYTES);
        attr_set = true;
    }

    // CSR build (dst-sorted); g_cnt is zero on entry (module init / k_scatter)
    k_hist<<<(E + 255) / 256, 256>>>(ei, E);
    k_scan1<<<ntiles, 1024>>>(N);
    k_scan3<<<(N + 255) / 256, 256>>>(N, E, ntiles);
    k_scatter<<<(E + 255) / 256, 256>>>(ei, E, N);

    // layer 1
    k_gemm1<<<(N + 127) / 128, 256, G1_SMEM_BYTES>>>(x, W1, atts1, attd1, N);
    k_agg1<<<(N * 32 + 255) / 256, 256>>>(N);

    // layer 2 + epilogue
    k_node2<<<(N + 255) / 256, 256>>>(W2, b1, atts2, attd2, N);
    k_agg2<<<(N * 16 + 255) / 256, 256>>>(b2, out, N);
}

// round 6
// speedup vs baseline: 1.4937x; 1.0212x over previous
#include <cuda_runtime.h>
#include <cstdint>

// ---------------------------------------------------------------------------
// GATNet 2-layer GAT, N=50000, E=800000 (+self loops).
// GEMM1 = 3xTF32 tensor-core (128x64 tile, dynamic smem, conflict-free frags)
// with fused attention logits. CSR-by-dst per call (shuffle scans, no zero
// launch); register aggregation, no float atomics.
// ---------------------------------------------------------------------------

#define NMAX 50000
#define EMAX 800000

__device__ __align__(16) float g_xl [NMAX * 64];
__device__ __align__(16) float g_as1[NMAX * 8];
__device__ __align__(16) float g_ad1[NMAX * 8];
__device__ __align__(16) float g_h  [NMAX * 64];
__device__ __align__(16) float g_hl2[NMAX * 16];
__device__ float g_as2[NMAX];
__device__ float g_ad2[NMAX];

__device__ int g_cnt [NMAX];   // zero at module load; re-zeroed by k_scatter
__device__ int g_inc [NMAX];
__device__ int g_bsum[64];
__device__ int g_rptr[NMAX + 1];
__device__ int g_fill[NMAX];
__device__ int g_col [EMAX];

__device__ __forceinline__ float leaky02(float a) { return fmaxf(a, 0.2f * a); }

__device__ __forceinline__ float tf32r(float x) {
    uint32_t u;
    asm("cvt.rna.tf32.f32 %0, %1;" : "=r"(u) : "f"(x));
    return __uint_as_float(u);
}

__device__ __forceinline__ void mma_tf32(float4& c, uint32_t a0, uint32_t a1,
                                         uint32_t a2, uint32_t a3,
                                         uint32_t b0, uint32_t b1) {
    asm volatile(
        "mma.sync.aligned.m16n8k8.row.col.f32.tf32.tf32.f32 "
        "{%0,%1,%2,%3}, {%4,%5,%6,%7}, {%8,%9}, {%0,%1,%2,%3};\n"
        : "+f"(c.x), "+f"(c.y), "+f"(c.z), "+f"(c.w)
        : "r"(a0), "r"(a1), "r"(a2), "r"(a3), "r"(b0), "r"(b1));
}

// ----------------------------- CSR construction ----------------------------
__global__ void k_hist(const int* __restrict__ ei, int E) {
    int e = blockIdx.x * blockDim.x + threadIdx.x;
    if (e < E) atomicAdd(&g_cnt[ei[E + e]], 1);
}

__global__ __launch_bounds__(1024) void k_scan1(int N) {
    __shared__ int sw[32];
    int t = threadIdx.x, i = blockIdx.x * 1024 + t;
    int lane = t & 31, wid = t >> 5;
    int s = (i < N) ? g_cnt[i] : 0;
#pragma unroll
    for (int o = 1; o < 32; o <<= 1) {
        int u = __shfl_up_sync(0xffffffffu, s, o);
        if (lane >= o) s += u;
    }
    if (lane == 31) sw[wid] = s;
    __syncthreads();
    if (wid == 0) {
        int ws = sw[lane];
#pragma unroll
        for (int o = 1; o < 32; o <<= 1) {
            int u = __shfl_up_sync(0xffffffffu, ws, o);
            if (lane >= o) ws += u;
        }
        sw[lane] = ws;
    }
    __syncthreads();
    int incl = s + (wid ? sw[wid - 1] : 0);
    if (i < N) g_inc[i] = incl;
    if (t == 1023) g_bsum[blockIdx.x] = incl;
}

// rptr = exclusive global offset; per-block single-warp scan of block sums
__global__ void k_scan3(int N, int E, int ntiles) {
    __shared__ int sh[64];
    int t = threadIdx.x;
    if (t < 32) {
        int a = (t < ntiles) ? g_bsum[t] : 0;
        int b = (t + 32 < ntiles) ? g_bsum[t + 32] : 0;
#pragma unroll
        for (int o = 1; o < 32; o <<= 1) {
            int u = __shfl_up_sync(0xffffffffu, a, o);
            if (t >= o) a += u;
        }
        int tot = __shfl_sync(0xffffffffu, a, 31);
#pragma unroll
        for (int o = 1; o < 32; o <<= 1) {
            int u = __shfl_up_sync(0xffffffffu, b, o);
            if (t >= o) b += u;
        }
        sh[t] = a;
        sh[t + 32] = b + tot;
    }
    __syncthreads();
    int i = blockIdx.x * blockDim.x + t;
    if (i < N) {
        int blk = i >> 10;
        int excl = blk ? sh[blk - 1] : 0;
        int rp = g_inc[i] - g_cnt[i] + excl;
        g_rptr[i] = rp;
        g_fill[i] = rp;
    }
    if (i == 0) g_rptr[N] = E;
}

__global__ void k_scatter(const int* __restrict__ ei, int E, int N) {
    int e = blockIdx.x * blockDim.x + threadIdx.x;
    if (e < N) g_cnt[e] = 0;   // reset for the next call (cnt dead after scan3)
    if (e >= E) return;
    int s = ei[e], d = ei[E + e];
    int pos = atomicAdd(&g_fill[d], 1);
    g_col[pos] = s;
}

// --------------- GEMM1 (3xTF32 MMA) + fused node1 logits -------------------
// xl = X @ W1, block tile 128x64, 8 warps = 4(M) x 2(N), warp tile 32x32.
#define G1_SMEM_BYTES (2 * 128 * 36 * 4 + 2 * 32 * 72 * 4)  // 55296

__global__ __launch_bounds__(256) void k_gemm1(const float* __restrict__ X,
                                               const float* __restrict__ W,
                                               const float* __restrict__ att_s,
                                               const float* __restrict__ att_d,
                                               int N) {
    extern __shared__ float smem[];
    float (*sAh)[36] = (float(*)[36])(smem);
    float (*sAl)[36] = (float(*)[36])(smem + 128 * 36);
    float (*sBh)[72] = (float(*)[72])(smem + 2 * 128 * 36);
    float (*sBl)[72] = (float(*)[72])(smem + 2 * 128 * 36 + 32 * 72);

    const int tid  = threadIdx.x;
    const int bm   = blockIdx.x * 128;
    const int warp = tid >> 5, lane = tid & 31;
    const int wm   = warp >> 1, wn = warp & 1;
    const int g    = lane >> 2, tig = lane & 3;

    // global loaders: A 128x32 (16 floats/thr), B 32x64 (8 floats/thr)
    const int ar = tid >> 1, ah = (tid & 1) * 16;
    const int bk = tid >> 3, bq = (tid & 7) * 8;

    int axr = bm + ar;
    if (axr >= N) axr = N - 1;  // clamp; stores guarded
    const float4* Xr = (const float4*)(X + (size_t)axr * 512);

    float4 acc[2][4];
#pragma unroll
    for (int i = 0; i < 2; i++)
#pragma unroll
        for (int j = 0; j < 4; j++) acc[i][j] = make_float4(0.f, 0.f, 0.f, 0.f);

    float4 ra[4], rb[2];
#pragma unroll
    for (int i = 0; i < 4; i++) ra[i] = Xr[(ah >> 2) + i];
#pragma unroll
    for (int i = 0; i < 2; i++)
        rb[i] = ((const float4*)(W + (size_t)bk * 64 + bq))[i];

    for (int ks = 0; ks < 16; ks++) {
#pragma unroll
        for (int i = 0; i < 4; i++) {
            float4 h4 = make_float4(tf32r(ra[i].x), tf32r(ra[i].y),
                                    tf32r(ra[i].z), tf32r(ra[i].w));
            float4 l4 = make_float4(tf32r(ra[i].x - h4.x), tf32r(ra[i].y - h4.y),
                                    tf32r(ra[i].z - h4.z), tf32r(ra[i].w - h4.w));
            *(float4*)&sAh[ar][ah + i * 4] = h4;
            *(float4*)&sAl[ar][ah + i * 4] = l4;
        }
#pragma unroll
        for (int i = 0; i < 2; i++) {
            float4 h4 = make_float4(tf32r(rb[i].x), tf32r(rb[i].y),
                                    tf32r(rb[i].z), tf32r(rb[i].w));
            float4 l4 = make_float4(tf32r(rb[i].x - h4.x), tf32r(rb[i].y - h4.y),
                                    tf32r(rb[i].z - h4.z), tf32r(rb[i].w - h4.w));
            *(float4*)&sBh[bk][bq + i * 4] = h4;
            *(float4*)&sBl[bk][bq + i * 4] = l4;
        }
        __syncthreads();
        if (ks < 15) {
            int k0 = (ks + 1) * 32;
#pragma unroll
            for (int i = 0; i < 4; i++) ra[i] = Xr[((k0 + ah) >> 2) + i];
#pragma unroll
            for (int i = 0; i < 2; i++)
                rb[i] = ((const float4*)(W + (size_t)(k0 + bk) * 64 + bq))[i];
        }
#pragma unroll
        for (int ksub = 0; ksub < 4; ksub++) {
            const int kc = ksub * 8;
            uint32_t Ah[2][4], Al[2][4];
#pragma unroll
            for (int mt = 0; mt < 2; mt++) {
                const int r0 = wm * 32 + mt * 16 + g, r1 = r0 + 8;
                Ah[mt][0] = __float_as_uint(sAh[r0][kc + tig]);
                Ah[mt][1] = __float_as_uint(sAh[r1][kc + tig]);
                Ah[mt][2] = __float_as_uint(sAh[r0][kc + tig + 4]);
                Ah[mt][3] = __float_as_uint(sAh[r1][kc + tig + 4]);
                Al[mt][0] = __float_as_uint(sAl[r0][kc + tig]);
                Al[mt][1] = __float_as_uint(sAl[r1][kc + tig]);
                Al[mt][2] = __float_as_uint(sAl[r0][kc + tig + 4]);
                Al[mt][3] = __float_as_uint(sAl[r1][kc + tig + 4]);
            }
#pragma unroll
            for (int nt = 0; nt < 4; nt++) {
                const int nc = wn * 32 + nt * 8 + g;
                uint32_t bh0 = __float_as_uint(sBh[kc + tig][nc]);
                uint32_t bh1 = __float_as_uint(sBh[kc + tig + 4][nc]);
                uint32_t bl0 = __float_as_uint(sBl[kc + tig][nc]);
                uint32_t bl1 = __float_as_uint(sBl[kc + tig + 4][nc]);
#pragma unroll
                for (int mt = 0; mt < 2; mt++) {
                    mma_tf32(acc[mt][nt], Al[mt][0], Al[mt][1], Al[mt][2],
                             Al[mt][3], bh0, bh1);
                    mma_tf32(acc[mt][nt], Ah[mt][0], Ah[mt][1], Ah[mt][2],
                             Ah[mt][3], bl0, bl1);
                    mma_tf32(acc[mt][nt], Ah[mt][0], Ah[mt][1], Ah[mt][2],
                             Ah[mt][3], bh0, bh1);
                }
            }
        }
        __syncthreads();
    }

#pragma unroll
    for (int mt = 0; mt < 2; mt++) {
        const int row0 = bm + wm * 32 + mt * 16 + g;
        const int row1 = row0 + 8;
        float s0a[4], s1a[4], d0a[4], d1a[4];
#pragma unroll
        for (int nt = 0; nt < 4; nt++) {
            const int h = wn * 4 + nt;
            const int col = h * 8 + tig * 2;
            float4 a = acc[mt][nt];
            if (row0 < N)
                *(float2*)&g_xl[(size_t)row0 * 64 + col] = make_float2(a.x, a.y);
            if (row1 < N)
                *(float2*)&g_xl[(size_t)row1 * 64 + col] = make_float2(a.z, a.w);

            float2 asv = make_float2(__ldg(att_s + h * 8 + 2 * tig),
                                     __ldg(att_s + h * 8 + 2 * tig + 1));
            float2 adv = make_float2(__ldg(att_d + h * 8 + 2 * tig),
                                     __ldg(att_d + h * 8 + 2 * tig + 1));
            float s0 = a.x * asv.x + a.y * asv.y;
            float s1 = a.z * asv.x + a.w * asv.y;
            float d0 = a.x * adv.x + a.y * adv.y;
            float d1 = a.z * adv.x + a.w * adv.y;
#pragma unroll
            for (int off = 1; off < 4; off <<= 1) {
                s0 += __shfl_xor_sync(0xffffffffu, s0, off);
                s1 += __shfl_xor_sync(0xffffffffu, s1, off);
                d0 += __shfl_xor_sync(0xffffffffu, d0, off);
                d1 += __shfl_xor_sync(0xffffffffu, d1, off);
            }
            s0a[nt] = s0; s1a[nt] = s1; d0a[nt] = d0; d1a[nt] = d1;
        }
        if (tig == 0) {
            if (row0 < N) {
                *(float4*)&g_as1[row0 * 8 + wn * 4] =
                    make_float4(s0a[0], s0a[1], s0a[2], s0a[3]);
                *(float4*)&g_ad1[row0 * 8 + wn * 4] =
                    make_float4(d0a[0], d0a[1], d0a[2], d0a[3]);
            }
            if (row1 < N) {
                *(float4*)&g_as1[row1 * 8 + wn * 4] =
                    make_float4(s1a[0], s1a[1], s1a[2], s1a[3]);
                *(float4*)&g_ad1[row1 * 8 + wn * 4] =
                    make_float4(d1a[0], d1a[1], d1a[2], d1a[3]);
            }
        }
    }
}

// ------------------- layer1 aggregation: warp per dst node ------------------
__global__ __launch_bounds__(256) void k_agg1(int N) {
    int warp = (blockIdx.x * blockDim.x + threadIdx.x) >> 5;
    int lane = threadIdx.x & 31;
    if (warp >= N) return;
    const int d = warp;
    const int h = lane >> 2;
    const float ad = g_ad1[d * 8 + h];

    float w = __expf(leaky02(g_as1[d * 8 + h] + ad));
    float2 v = *(const float2*)&g_xl[(size_t)d * 64 + lane * 2];
    float nx = w * v.x, ny = w * v.y;
    float den = ((lane & 3) == 0) ? w : 0.f;

    const int e1 = g_rptr[d + 1];
#pragma unroll 4
    for (int e = g_rptr[d]; e < e1; e++) {
        int s = g_col[e];
        float we = __expf(leaky02(g_as1[s * 8 + h] + ad));
        float2 xs = *(const float2*)&g_xl[(size_t)s * 64 + lane * 2];
        nx += we * xs.x;
        ny += we * xs.y;
        if ((lane & 3) == 0) den += we;
    }
    float dfull = __shfl_sync(0xffffffffu, den, lane & ~3) + 1e-16f;
    float inv = 1.f / dfull;
    *(float2*)&g_h[(size_t)d * 64 + lane * 2] = make_float2(nx * inv, ny * inv);
}

// -------- layer1 bias + GEMM2 + per-node logits (layer2) -------------------
__global__ void k_node2(const float* __restrict__ W2,
                        const float* __restrict__ b1,
                        const float* __restrict__ att_s2,
                        const float* __restrict__ att_d2, int N) {
    int n = blockIdx.x * blockDim.x + threadIdx.x;
    if (n >= N) return;
    float acc[16];
#pragma unroll
    for (int c = 0; c < 16; c++) acc[c] = 0.f;
    const float* hrow = g_h + (size_t)n * 64;
#pragma unroll 4
    for (int j = 0; j < 64; j++) {
        float hj = hrow[j] + __ldg(b1 + j);
        const float* wrow = W2 + j * 16;
#pragma unroll
        for (int c = 0; c < 16; c++) acc[c] += hj * __ldg(wrow + c);
    }
    float sa = 0.f, sd = 0.f;
#pragma unroll
    for (int c = 0; c < 16; c++) {
        g_hl2[n * 16 + c] = acc[c];
        sa += acc[c] * __ldg(att_s2 + c);
        sd += acc[c] * __ldg(att_d2 + c);
    }
    g_as2[n] = sa;
    g_ad2[n] = sd;
}

// ------ layer2 aggregation + bias + elu + log_softmax (16 lanes/node) ------
__global__ __launch_bounds__(256) void k_agg2(const float* __restrict__ b2,
                                              float* __restrict__ out, int N) {
    int gid = (blockIdx.x * blockDim.x + threadIdx.x) >> 4;
    int c = threadIdx.x & 15;
    bool valid = gid < N;
    const int d = valid ? gid : 0;
    const float ad = g_ad2[d];

    float w = __expf(leaky02(g_as2[d] + ad));
    float num = w * g_hl2[(size_t)d * 16 + c];
    float den = w;

    const int e1 = g_rptr[d + 1];
#pragma unroll 4
    for (int e = g_rptr[d]; e < e1; e++) {
        int s = g_col[e];
        float we = __expf(leaky02(g_as2[s] + ad));
        num += we * g_hl2[(size_t)s * 16 + c];
        den += we;
    }
    float x = num / (den + 1e-16f) + __ldg(b2 + c);
    x = (x > 0.f) ? x : (__expf(x) - 1.f);

    float m = x;
#pragma unroll
    for (int off = 1; off < 16; off <<= 1)
        m = fmaxf(m, __shfl_xor_sync(0xffffffffu, m, off));
    float ssum = __expf(x - m);
#pragma unroll
    for (int off = 1; off < 16; off <<= 1)
        ssum += __shfl_xor_sync(0xffffffffu, ssum, off);
    if (valid) out[(size_t)d * 16 + c] = x - m - __logf(ssum);
}

// ---------------------------------------------------------------------------
extern "C" void kernel_launch(void* const* d_in, const int* in_sizes, int n_in,
                              void* d_out, int out_size) {
    const float* x     = (const float*)d_in[0];
    const int*   ei    = (const int*)d_in[1];
    const float* W1    = (const float*)d_in[2];
    const float* atts1 = (const float*)d_in[3];
    const float* attd1 = (const float*)d_in[4];
    const float* b1    = (const float*)d_in[5];
    const float* W2    = (const float*)d_in[6];
    const float* atts2 = (const float*)d_in[7];
    const float* attd2 = (const float*)d_in[8];
    const float* b2    = (const float*)d_in[9];
    float* out = (float*)d_out;

    const int N = in_sizes[0] / 512;
    const int E = in_sizes[1] / 2;
    const int ntiles = (N + 1023) >> 10;

    static bool attr_set = false;
    if (!attr_set) {
        cudaFuncSetAttribute(k_gemm1, cudaFuncAttributeMaxDynamicSharedMemorySize,
                             G1_SMEM_BYTES);
        attr_set = true;
    }

    // CSR build (dst-sorted); g_cnt is zero on entry (module init / k_scatter)
    k_hist<<<(E + 255) / 256, 256>>>(ei, E);
    k_scan1<<<ntiles, 1024>>>(N);
    k_scan3<<<(N + 255) / 256, 256>>>(N, E, ntiles);
    k_scatter<<<(E + 255) / 256, 256>>>(ei, E, N);

    // layer 1
    k_gemm1<<<(N + 127) / 128, 256, G1_SMEM_BYTES>>>(x, W1, atts1, attd1, N);
    k_agg1<<<(N * 32 + 255) / 256, 256>>>(N);

    // layer 2 + epilogue
    k_node2<<<(N + 255) / 256, 256>>>(W2, b1, atts2, attd2, N);
    k_agg2<<<(N * 16 + 255) / 256, 256>>>(b2, out, N);
}

// round 7
// speedup vs baseline: 1.7123x; 1.1464x over previous
#include <cuda_runtime.h>
#include <cstdint>

// ---------------------------------------------------------------------------
// GATNet 2-layer GAT, N=50000, E=800000 (+self loops).
// GEMM1 = 3xTF32 tensor-core (128x64 tile) with fused attention logits.
// CSR-by-dst per call (rank captured in hist -> atomic-free scatter).
// agg1 fuses layer-1 aggregation + bias + layer-2 GEMM + layer-2 logits.
// ---------------------------------------------------------------------------

#define NMAX 50000
#define EMAX 800000

__device__ __align__(16) float g_xl [NMAX * 64];
__device__ __align__(16) float g_as1[NMAX * 8];
__device__ __align__(16) float g_ad1[NMAX * 8];
__device__ __align__(16) float g_hl2[NMAX * 16];
__device__ float g_as2[NMAX];
__device__ float g_ad2[NMAX];

__device__ int g_cnt [NMAX];   // zero at module load; re-zeroed by k_scatter
__device__ int g_inc [NMAX];
__device__ int g_bsum[64];
__device__ int g_rptr[NMAX + 1];
__device__ int g_rank[EMAX];
__device__ int g_col [EMAX];

__device__ __forceinline__ float leaky02(float a) { return fmaxf(a, 0.2f * a); }

__device__ __forceinline__ float tf32r(float x) {
    uint32_t u;
    asm("cvt.rna.tf32.f32 %0, %1;" : "=r"(u) : "f"(x));
    return __uint_as_float(u);
}

__device__ __forceinline__ void mma_tf32(float4& c, uint32_t a0, uint32_t a1,
                                         uint32_t a2, uint32_t a3,
                                         uint32_t b0, uint32_t b1) {
    asm volatile(
        "mma.sync.aligned.m16n8k8.row.col.f32.tf32.tf32.f32 "
        "{%0,%1,%2,%3}, {%4,%5,%6,%7}, {%8,%9}, {%0,%1,%2,%3};\n"
        : "+f"(c.x), "+f"(c.y), "+f"(c.z), "+f"(c.w)
        : "r"(a0), "r"(a1), "r"(a2), "r"(a3), "r"(b0), "r"(b1));
}

// ----------------------------- CSR construction ----------------------------
// hist also records each edge's rank within its dst bucket.
__global__ void k_hist(const int* __restrict__ ei, int E) {
    int e = blockIdx.x * blockDim.x + threadIdx.x;
    if (e < E) g_rank[e] = atomicAdd(&g_cnt[ei[E + e]], 1);
}

__global__ __launch_bounds__(1024) void k_scan1(int N) {
    __shared__ int sw[32];
    int t = threadIdx.x, i = blockIdx.x * 1024 + t;
    int lane = t & 31, wid = t >> 5;
    int s = (i < N) ? g_cnt[i] : 0;
#pragma unroll
    for (int o = 1; o < 32; o <<= 1) {
        int u = __shfl_up_sync(0xffffffffu, s, o);
        if (lane >= o) s += u;
    }
    if (lane == 31) sw[wid] = s;
    __syncthreads();
    if (wid == 0) {
        int ws = sw[lane];
#pragma unroll
        for (int o = 1; o < 32; o <<= 1) {
            int u = __shfl_up_sync(0xffffffffu, ws, o);
            if (lane >= o) ws += u;
        }
        sw[lane] = ws;
    }
    __syncthreads();
    int incl = s + (wid ? sw[wid - 1] : 0);
    if (i < N) g_inc[i] = incl;
    if (t == 1023) g_bsum[blockIdx.x] = incl;
}

__global__ void k_scan3(int N, int E, int ntiles) {
    __shared__ int sh[64];
    int t = threadIdx.x;
    if (t < 32) {
        int a = (t < ntiles) ? g_bsum[t] : 0;
        int b = (t + 32 < ntiles) ? g_bsum[t + 32] : 0;
#pragma unroll
        for (int o = 1; o < 32; o <<= 1) {
            int u = __shfl_up_sync(0xffffffffu, a, o);
            if (t >= o) a += u;
        }
        int tot = __shfl_sync(0xffffffffu, a, 31);
#pragma unroll
        for (int o = 1; o < 32; o <<= 1) {
            int u = __shfl_up_sync(0xffffffffu, b, o);
            if (t >= o) b += u;
        }
        sh[t] = a;
        sh[t + 32] = b + tot;
    }
    __syncthreads();
    int i = blockIdx.x * blockDim.x + t;
    if (i < N) {
        int blk = i >> 10;
        int excl = blk ? sh[blk - 1] : 0;
        g_rptr[i] = g_inc[i] - g_cnt[i] + excl;
    }
    if (i == 0) g_rptr[N] = E;
}

// atomic-free scatter: slot = rptr[d] + rank[e]; also re-zero g_cnt.
__global__ void k_scatter(const int* __restrict__ ei, int E, int N) {
    int e = blockIdx.x * blockDim.x + threadIdx.x;
    if (e < N) g_cnt[e] = 0;
    if (e >= E) return;
    int d = ei[E + e];
    g_col[g_rptr[d] + g_rank[e]] = ei[e];
}

// --------------- GEMM1 (3xTF32 MMA) + fused node1 logits -------------------
#define G1_SMEM_BYTES (2 * 128 * 36 * 4 + 2 * 32 * 72 * 4)  // 55296

__global__ __launch_bounds__(256) void k_gemm1(const float* __restrict__ X,
                                               const float* __restrict__ W,
                                               const float* __restrict__ att_s,
                                               const float* __restrict__ att_d,
                                               int N) {
    extern __shared__ float smem[];
    float (*sAh)[36] = (float(*)[36])(smem);
    float (*sAl)[36] = (float(*)[36])(smem + 128 * 36);
    float (*sBh)[72] = (float(*)[72])(smem + 2 * 128 * 36);
    float (*sBl)[72] = (float(*)[72])(smem + 2 * 128 * 36 + 32 * 72);

    const int tid  = threadIdx.x;
    const int bm   = blockIdx.x * 128;
    const int warp = tid >> 5, lane = tid & 31;
    const int wm   = warp >> 1, wn = warp & 1;
    const int g    = lane >> 2, tig = lane & 3;

    const int ar = tid >> 1, ah = (tid & 1) * 16;
    const int bk = tid >> 3, bq = (tid & 7) * 8;

    int axr = bm + ar;
    if (axr >= N) axr = N - 1;
    const float4* Xr = (const float4*)(X + (size_t)axr * 512);

    float4 acc[2][4];
#pragma unroll
    for (int i = 0; i < 2; i++)
#pragma unroll
        for (int j = 0; j < 4; j++) acc[i][j] = make_float4(0.f, 0.f, 0.f, 0.f);

    float4 ra[4], rb[2];
#pragma unroll
    for (int i = 0; i < 4; i++) ra[i] = Xr[(ah >> 2) + i];
#pragma unroll
    for (int i = 0; i < 2; i++)
        rb[i] = ((const float4*)(W + (size_t)bk * 64 + bq))[i];

    for (int ks = 0; ks < 16; ks++) {
#pragma unroll
        for (int i = 0; i < 4; i++) {
            float4 h4 = make_float4(tf32r(ra[i].x), tf32r(ra[i].y),
                                    tf32r(ra[i].z), tf32r(ra[i].w));
            float4 l4 = make_float4(tf32r(ra[i].x - h4.x), tf32r(ra[i].y - h4.y),
                                    tf32r(ra[i].z - h4.z), tf32r(ra[i].w - h4.w));
            *(float4*)&sAh[ar][ah + i * 4] = h4;
            *(float4*)&sAl[ar][ah + i * 4] = l4;
        }
#pragma unroll
        for (int i = 0; i < 2; i++) {
            float4 h4 = make_float4(tf32r(rb[i].x), tf32r(rb[i].y),
                                    tf32r(rb[i].z), tf32r(rb[i].w));
            float4 l4 = make_float4(tf32r(rb[i].x - h4.x), tf32r(rb[i].y - h4.y),
                                    tf32r(rb[i].z - h4.z), tf32r(rb[i].w - h4.w));
            *(float4*)&sBh[bk][bq + i * 4] = h4;
            *(float4*)&sBl[bk][bq + i * 4] = l4;
        }
        __syncthreads();
        if (ks < 15) {
            int k0 = (ks + 1) * 32;
#pragma unroll
            for (int i = 0; i < 4; i++) ra[i] = Xr[((k0 + ah) >> 2) + i];
#pragma unroll
            for (int i = 0; i < 2; i++)
                rb[i] = ((const float4*)(W + (size_t)(k0 + bk) * 64 + bq))[i];
        }
#pragma unroll
        for (int ksub = 0; ksub < 4; ksub++) {
            const int kc = ksub * 8;
            uint32_t Ah[2][4], Al[2][4];
#pragma unroll
            for (int mt = 0; mt < 2; mt++) {
                const int r0 = wm * 32 + mt * 16 + g, r1 = r0 + 8;
                Ah[mt][0] = __float_as_uint(sAh[r0][kc + tig]);
                Ah[mt][1] = __float_as_uint(sAh[r1][kc + tig]);
                Ah[mt][2] = __float_as_uint(sAh[r0][kc + tig + 4]);
                Ah[mt][3] = __float_as_uint(sAh[r1][kc + tig + 4]);
                Al[mt][0] = __float_as_uint(sAl[r0][kc + tig]);
                Al[mt][1] = __float_as_uint(sAl[r1][kc + tig]);
                Al[mt][2] = __float_as_uint(sAl[r0][kc + tig + 4]);
                Al[mt][3] = __float_as_uint(sAl[r1][kc + tig + 4]);
            }
#pragma unroll
            for (int nt = 0; nt < 4; nt++) {
                const int nc = wn * 32 + nt * 8 + g;
                uint32_t bh0 = __float_as_uint(sBh[kc + tig][nc]);
                uint32_t bh1 = __float_as_uint(sBh[kc + tig + 4][nc]);
                uint32_t bl0 = __float_as_uint(sBl[kc + tig][nc]);
                uint32_t bl1 = __float_as_uint(sBl[kc + tig + 4][nc]);
#pragma unroll
                for (int mt = 0; mt < 2; mt++) {
                    mma_tf32(acc[mt][nt], Al[mt][0], Al[mt][1], Al[mt][2],
                             Al[mt][3], bh0, bh1);
                    mma_tf32(acc[mt][nt], Ah[mt][0], Ah[mt][1], Ah[mt][2],
                             Ah[mt][3], bl0, bl1);
                    mma_tf32(acc[mt][nt], Ah[mt][0], Ah[mt][1], Ah[mt][2],
                             Ah[mt][3], bh0, bh1);
                }
            }
        }
        __syncthreads();
    }

#pragma unroll
    for (int mt = 0; mt < 2; mt++) {
        const int row0 = bm + wm * 32 + mt * 16 + g;
        const int row1 = row0 + 8;
        float s0a[4], s1a[4], d0a[4], d1a[4];
#pragma unroll
        for (int nt = 0; nt < 4; nt++) {
            const int h = wn * 4 + nt;
            const int col = h * 8 + tig * 2;
            float4 a = acc[mt][nt];
            if (row0 < N)
                *(float2*)&g_xl[(size_t)row0 * 64 + col] = make_float2(a.x, a.y);
            if (row1 < N)
                *(float2*)&g_xl[(size_t)row1 * 64 + col] = make_float2(a.z, a.w);

            float2 asv = make_float2(__ldg(att_s + h * 8 + 2 * tig),
                                     __ldg(att_s + h * 8 + 2 * tig + 1));
            float2 adv = make_float2(__ldg(att_d + h * 8 + 2 * tig),
                                     __ldg(att_d + h * 8 + 2 * tig + 1));
            float s0 = a.x * asv.x + a.y * asv.y;
            float s1 = a.z * asv.x + a.w * asv.y;
            float d0 = a.x * adv.x + a.y * adv.y;
            float d1 = a.z * adv.x + a.w * adv.y;
#pragma unroll
            for (int off = 1; off < 4; off <<= 1) {
                s0 += __shfl_xor_sync(0xffffffffu, s0, off);
                s1 += __shfl_xor_sync(0xffffffffu, s1, off);
                d0 += __shfl_xor_sync(0xffffffffu, d0, off);
                d1 += __shfl_xor_sync(0xffffffffu, d1, off);
            }
            s0a[nt] = s0; s1a[nt] = s1; d0a[nt] = d0; d1a[nt] = d1;
        }
        if (tig == 0) {
            if (row0 < N) {
                *(float4*)&g_as1[row0 * 8 + wn * 4] =
                    make_float4(s0a[0], s0a[1], s0a[2], s0a[3]);
                *(float4*)&g_ad1[row0 * 8 + wn * 4] =
                    make_float4(d0a[0], d0a[1], d0a[2], d0a[3]);
            }
            if (row1 < N) {
                *(float4*)&g_as1[row1 * 8 + wn * 4] =
                    make_float4(s1a[0], s1a[1], s1a[2], s1a[3]);
                *(float4*)&g_ad1[row1 * 8 + wn * 4] =
                    make_float4(d1a[0], d1a[1], d1a[2], d1a[3]);
            }
        }
    }
}

// ---- layer1 aggregation + bias + layer2 GEMM + layer2 logits (fused) ------
// Warp per dst node. Lane l accumulates features {2l, 2l+1} (head = l>>2).
// Epilogue: h row -> per-warp smem, lanes 0..15 compute hl2 cols + as2/ad2.
__global__ __launch_bounds__(256) void k_agg1(const float* __restrict__ b1,
                                              const float* __restrict__ W2,
                                              const float* __restrict__ atts2,
                                              const float* __restrict__ attd2,
                                              int N) {
    __shared__ float sh[8][64];
    int warp = (blockIdx.x * blockDim.x + threadIdx.x) >> 5;
    int wl = (threadIdx.x >> 5);
    int lane = threadIdx.x & 31;
    if (warp >= N) return;
    const int d = warp;
    const int h = lane >> 2;
    const float ad = g_ad1[d * 8 + h];

    float w = __expf(leaky02(g_as1[d * 8 + h] + ad));
    float2 v = *(const float2*)&g_xl[(size_t)d * 64 + lane * 2];
    float nx = w * v.x, ny = w * v.y;
    float den = ((lane & 3) == 0) ? w : 0.f;

    const int e1 = g_rptr[d + 1];
#pragma unroll 4
    for (int e = g_rptr[d]; e < e1; e++) {
        int s = g_col[e];
        float we = __expf(leaky02(g_as1[s * 8 + h] + ad));
        float2 xs = *(const float2*)&g_xl[(size_t)s * 64 + lane * 2];
        nx += we * xs.x;
        ny += we * xs.y;
        if ((lane & 3) == 0) den += we;
    }
    float dfull = __shfl_sync(0xffffffffu, den, lane & ~3) + 1e-16f;
    float inv = 1.f / dfull;

    // h row (bias folded) into per-warp smem
    sh[wl][lane * 2]     = nx * inv + __ldg(b1 + lane * 2);
    sh[wl][lane * 2 + 1] = ny * inv + __ldg(b1 + lane * 2 + 1);
    __syncwarp();

    // layer2 GEMM column per lane (lanes 0..15), broadcast smem reads
    if (lane < 16) {
        float y0 = 0.f, y1 = 0.f;
#pragma unroll
        for (int j = 0; j < 64; j += 2) {
            y0 += sh[wl][j]     * __ldg(W2 + j * 16 + lane);
            y1 += sh[wl][j + 1] * __ldg(W2 + (j + 1) * 16 + lane);
        }
        float y = y0 + y1;
        g_hl2[(size_t)d * 16 + lane] = y;
        float pa = y * __ldg(atts2 + lane);
        float pd = y * __ldg(attd2 + lane);
#pragma unroll
        for (int off = 8; off >= 1; off >>= 1) {
            pa += __shfl_xor_sync(0x0000ffffu, pa, off);
            pd += __shfl_xor_sync(0x0000ffffu, pd, off);
        }
        if (lane == 0) {
            g_as2[d] = pa;
            g_ad2[d] = pd;
        }
    }
}

// ------ layer2 aggregation + bias + elu + log_softmax (16 lanes/node) ------
__global__ __launch_bounds__(256) void k_agg2(const float* __restrict__ b2,
                                              float* __restrict__ out, int N) {
    int gid = (blockIdx.x * blockDim.x + threadIdx.x) >> 4;
    int c = threadIdx.x & 15;
    bool valid = gid < N;
    const int d = valid ? gid : 0;
    const float ad = g_ad2[d];

    float w = __expf(leaky02(g_as2[d] + ad));
    float num = w * g_hl2[(size_t)d * 16 + c];
    float den = w;

    const int e1 = g_rptr[d + 1];
#pragma unroll 4
    for (int e = g_rptr[d]; e < e1; e++) {
        int s = g_col[e];
        float we = __expf(leaky02(g_as2[s] + ad));
        num += we * g_hl2[(size_t)s * 16 + c];
        den += we;
    }
    float x = num / (den + 1e-16f) + __ldg(b2 + c);
    x = (x > 0.f) ? x : (__expf(x) - 1.f);

    float m = x;
#pragma unroll
    for (int off = 1; off < 16; off <<= 1)
        m = fmaxf(m, __shfl_xor_sync(0xffffffffu, m, off));
    float ssum = __expf(x - m);
#pragma unroll
    for (int off = 1; off < 16; off <<= 1)
        ssum += __shfl_xor_sync(0xffffffffu, ssum, off);
    if (valid) out[(size_t)d * 16 + c] = x - m - __logf(ssum);
}

// ---------------------------------------------------------------------------
extern "C" void kernel_launch(void* const* d_in, const int* in_sizes, int n_in,
                              void* d_out, int out_size) {
    const float* x     = (const float*)d_in[0];
    const int*   ei    = (const int*)d_in[1];
    const float* W1    = (const float*)d_in[2];
    const float* atts1 = (const float*)d_in[3];
    const float* attd1 = (const float*)d_in[4];
    const float* b1    = (const float*)d_in[5];
    const float* W2    = (const float*)d_in[6];
    const float* atts2 = (const float*)d_in[7];
    const float* attd2 = (const float*)d_in[8];
    const float* b2    = (const float*)d_in[9];
    float* out = (float*)d_out;

    const int N = in_sizes[0] / 512;
    const int E = in_sizes[1] / 2;
    const int ntiles = (N + 1023) >> 10;

    static bool attr_set = false;
    if (!attr_set) {
        cudaFuncSetAttribute(k_gemm1, cudaFuncAttributeMaxDynamicSharedMemorySize,
                             G1_SMEM_BYTES);
        attr_set = true;
    }

    // CSR build (dst-sorted); g_cnt is zero on entry
    k_hist<<<(E + 255) / 256, 256>>>(ei, E);
    k_scan1<<<ntiles, 1024>>>(N);
    k_scan3<<<(N + 255) / 256, 256>>>(N, E, ntiles);
    k_scatter<<<(E + 255) / 256, 256>>>(ei, E, N);

    // layer 1 GEMM + logits
    k_gemm1<<<(N + 127) / 128, 256, G1_SMEM_BYTES>>>(x, W1, atts1, attd1, N);

    // layer1 aggregation fused with layer2 GEMM/logits
    k_agg1<<<(N * 32 + 255) / 256, 256>>>(b1, W2, atts2, attd2, N);

    // layer2 aggregation + epilogue
    k_agg2<<<(N * 16 + 255) / 256, 256>>>(b2, out, N);
}

// round 8
// speedup vs baseline: 1.9124x; 1.1168x over previous
#include <cuda_runtime.h>
#include <cstdint>

// ---------------------------------------------------------------------------
// GATNet 2-layer GAT, N=50000, E=800000 (+self loops).
// GEMM1 = 3xTF32 tensor-core (128x64 tile) with fused attention logits.
// CSR-by-dst per call (rank captured in hist -> atomic-free scatter), built
// on a second stream overlapped with GEMM1 (fork-join inside the graph).
// agg1 fuses layer-1 aggregation + bias + layer-2 GEMM + layer-2 logits.
// ---------------------------------------------------------------------------

#define NMAX 50000
#define EMAX 800000

__device__ __align__(16) float g_xl [NMAX * 64];
__device__ __align__(16) float g_as1[NMAX * 8];
__device__ __align__(16) float g_ad1[NMAX * 8];
__device__ __align__(16) float g_hl2[NMAX * 16];
__device__ float g_as2[NMAX];
__device__ float g_ad2[NMAX];

__device__ int g_cnt [NMAX];   // zero at module load; re-zeroed by k_scatter
__device__ int g_inc [NMAX];
__device__ int g_bsum[64];
__device__ int g_rptr[NMAX + 1];
__device__ int g_rank[EMAX];
__device__ int g_col [EMAX];

__device__ __forceinline__ float leaky02(float a) { return fmaxf(a, 0.2f * a); }

__device__ __forceinline__ float tf32r(float x) {
    uint32_t u;
    asm("cvt.rna.tf32.f32 %0, %1;" : "=r"(u) : "f"(x));
    return __uint_as_float(u);
}

__device__ __forceinline__ void mma_tf32(float4& c, uint32_t a0, uint32_t a1,
                                         uint32_t a2, uint32_t a3,
                                         uint32_t b0, uint32_t b1) {
    asm volatile(
        "mma.sync.aligned.m16n8k8.row.col.f32.tf32.tf32.f32 "
        "{%0,%1,%2,%3}, {%4,%5,%6,%7}, {%8,%9}, {%0,%1,%2,%3};\n"
        : "+f"(c.x), "+f"(c.y), "+f"(c.z), "+f"(c.w)
        : "r"(a0), "r"(a1), "r"(a2), "r"(a3), "r"(b0), "r"(b1));
}

// ----------------------------- CSR construction ----------------------------
// hist: 4 edges/thread, records each edge's rank within its dst bucket.
__global__ void k_hist(const int* __restrict__ ei, int E) {
    int base = (blockIdx.x * blockDim.x + threadIdx.x) * 4;
    if (base >= E) return;
    int m = E - base; if (m > 4) m = 4;
    int d[4];
#pragma unroll
    for (int i = 0; i < 4; i++) if (i < m) d[i] = ei[E + base + i];
#pragma unroll
    for (int i = 0; i < 4; i++)
        if (i < m) g_rank[base + i] = atomicAdd(&g_cnt[d[i]], 1);
}

__global__ __launch_bounds__(1024) void k_scan1(int N) {
    __shared__ int sw[32];
    int t = threadIdx.x, i = blockIdx.x * 1024 + t;
    int lane = t & 31, wid = t >> 5;
    int s = (i < N) ? g_cnt[i] : 0;
#pragma unroll
    for (int o = 1; o < 32; o <<= 1) {
        int u = __shfl_up_sync(0xffffffffu, s, o);
        if (lane >= o) s += u;
    }
    if (lane == 31) sw[wid] = s;
    __syncthreads();
    if (wid == 0) {
        int ws = sw[lane];
#pragma unroll
        for (int o = 1; o < 32; o <<= 1) {
            int u = __shfl_up_sync(0xffffffffu, ws, o);
            if (lane >= o) ws += u;
        }
        sw[lane] = ws;
    }
    __syncthreads();
    int incl = s + (wid ? sw[wid - 1] : 0);
    if (i < N) g_inc[i] = incl;
    if (t == 1023) g_bsum[blockIdx.x] = incl;
}

__global__ void k_scan3(int N, int E, int ntiles) {
    __shared__ int sh[64];
    int t = threadIdx.x;
    if (t < 32) {
        int a = (t < ntiles) ? g_bsum[t] : 0;
        int b = (t + 32 < ntiles) ? g_bsum[t + 32] : 0;
#pragma unroll
        for (int o = 1; o < 32; o <<= 1) {
            int u = __shfl_up_sync(0xffffffffu, a, o);
            if (t >= o) a += u;
        }
        int tot = __shfl_sync(0xffffffffu, a, 31);
#pragma unroll
        for (int o = 1; o < 32; o <<= 1) {
            int u = __shfl_up_sync(0xffffffffu, b, o);
            if (t >= o) b += u;
        }
        sh[t] = a;
        sh[t + 32] = b + tot;
    }
    __syncthreads();
    int i = blockIdx.x * blockDim.x + t;
    if (i < N) {
        int blk = i >> 10;
        int excl = blk ? sh[blk - 1] : 0;
        g_rptr[i] = g_inc[i] - g_cnt[i] + excl;
    }
    if (i == 0) g_rptr[N] = E;
}

// atomic-free scatter, 4 edges/thread (batched gathers); also re-zero g_cnt.
__global__ void k_scatter(const int* __restrict__ ei, int E, int N) {
    int tid = blockIdx.x * blockDim.x + threadIdx.x;
    if (tid < N) g_cnt[tid] = 0;
    int base = tid * 4;
    if (base >= E) return;
    int m = E - base; if (m > 4) m = 4;
    int d[4], s[4], r[4], rp[4];
#pragma unroll
    for (int i = 0; i < 4; i++)
        if (i < m) { d[i] = ei[E + base + i]; s[i] = ei[base + i]; }
#pragma unroll
    for (int i = 0; i < 4; i++) if (i < m) r[i] = g_rank[base + i];
#pragma unroll
    for (int i = 0; i < 4; i++) if (i < m) rp[i] = g_rptr[d[i]];
#pragma unroll
    for (int i = 0; i < 4; i++) if (i < m) g_col[rp[i] + r[i]] = s[i];
}

// --------------- GEMM1 (3xTF32 MMA) + fused node1 logits -------------------
#define G1_SMEM_BYTES (2 * 128 * 36 * 4 + 2 * 32 * 72 * 4)  // 55296

__global__ __launch_bounds__(256) void k_gemm1(const float* __restrict__ X,
                                               const float* __restrict__ W,
                                               const float* __restrict__ att_s,
                                               const float* __restrict__ att_d,
                                               int N) {
    extern __shared__ float smem[];
    float (*sAh)[36] = (float(*)[36])(smem);
    float (*sAl)[36] = (float(*)[36])(smem + 128 * 36);
    float (*sBh)[72] = (float(*)[72])(smem + 2 * 128 * 36);
    float (*sBl)[72] = (float(*)[72])(smem + 2 * 128 * 36 + 32 * 72);

    const int tid  = threadIdx.x;
    const int bm   = blockIdx.x * 128;
    const int warp = tid >> 5, lane = tid & 31;
    const int wm   = warp >> 1, wn = warp & 1;
    const int g    = lane >> 2, tig = lane & 3;

    const int ar = tid >> 1, ah = (tid & 1) * 16;
    const int bk = tid >> 3, bq = (tid & 7) * 8;

    int axr = bm + ar;
    if (axr >= N) axr = N - 1;
    const float4* Xr = (const float4*)(X + (size_t)axr * 512);

    float4 acc[2][4];
#pragma unroll
    for (int i = 0; i < 2; i++)
#pragma unroll
        for (int j = 0; j < 4; j++) acc[i][j] = make_float4(0.f, 0.f, 0.f, 0.f);

    float4 ra[4], rb[2];
#pragma unroll
    for (int i = 0; i < 4; i++) ra[i] = Xr[(ah >> 2) + i];
#pragma unroll
    for (int i = 0; i < 2; i++)
        rb[i] = ((const float4*)(W + (size_t)bk * 64 + bq))[i];

    for (int ks = 0; ks < 16; ks++) {
#pragma unroll
        for (int i = 0; i < 4; i++) {
            float4 h4 = make_float4(tf32r(ra[i].x), tf32r(ra[i].y),
                                    tf32r(ra[i].z), tf32r(ra[i].w));
            float4 l4 = make_float4(tf32r(ra[i].x - h4.x), tf32r(ra[i].y - h4.y),
                                    tf32r(ra[i].z - h4.z), tf32r(ra[i].w - h4.w));
            *(float4*)&sAh[ar][ah + i * 4] = h4;
            *(float4*)&sAl[ar][ah + i * 4] = l4;
        }
#pragma unroll
        for (int i = 0; i < 2; i++) {
            float4 h4 = make_float4(tf32r(rb[i].x), tf32r(rb[i].y),
                                    tf32r(rb[i].z), tf32r(rb[i].w));
            float4 l4 = make_float4(tf32r(rb[i].x - h4.x), tf32r(rb[i].y - h4.y),
                                    tf32r(rb[i].z - h4.z), tf32r(rb[i].w - h4.w));
            *(float4*)&sBh[bk][bq + i * 4] = h4;
            *(float4*)&sBl[bk][bq + i * 4] = l4;
        }
        __syncthreads();
        if (ks < 15) {
            int k0 = (ks + 1) * 32;
#pragma unroll
            for (int i = 0; i < 4; i++) ra[i] = Xr[((k0 + ah) >> 2) + i];
#pragma unroll
            for (int i = 0; i < 2; i++)
                rb[i] = ((const float4*)(W + (size_t)(k0 + bk) * 64 + bq))[i];
        }
#pragma unroll
        for (int ksub = 0; ksub < 4; ksub++) {
            const int kc = ksub * 8;
            uint32_t Ah[2][4], Al[2][4];
#pragma unroll
            for (int mt = 0; mt < 2; mt++) {
                const int r0 = wm * 32 + mt * 16 + g, r1 = r0 + 8;
                Ah[mt][0] = __float_as_uint(sAh[r0][kc + tig]);
                Ah[mt][1] = __float_as_uint(sAh[r1][kc + tig]);
                Ah[mt][2] = __float_as_uint(sAh[r0][kc + tig + 4]);
                Ah[mt][3] = __float_as_uint(sAh[r1][kc + tig + 4]);
                Al[mt][0] = __float_as_uint(sAl[r0][kc + tig]);
                Al[mt][1] = __float_as_uint(sAl[r1][kc + tig]);
                Al[mt][2] = __float_as_uint(sAl[r0][kc + tig + 4]);
                Al[mt][3] = __float_as_uint(sAl[r1][kc + tig + 4]);
            }
#pragma unroll
            for (int nt = 0; nt < 4; nt++) {
                const int nc = wn * 32 + nt * 8 + g;
                uint32_t bh0 = __float_as_uint(sBh[kc + tig][nc]);
                uint32_t bh1 = __float_as_uint(sBh[kc + tig + 4][nc]);
                uint32_t bl0 = __float_as_uint(sBl[kc + tig][nc]);
                uint32_t bl1 = __float_as_uint(sBl[kc + tig + 4][nc]);
#pragma unroll
                for (int mt = 0; mt < 2; mt++) {
                    mma_tf32(acc[mt][nt], Al[mt][0], Al[mt][1], Al[mt][2],
                             Al[mt][3], bh0, bh1);
                    mma_tf32(acc[mt][nt], Ah[mt][0], Ah[mt][1], Ah[mt][2],
                             Ah[mt][3], bl0, bl1);
                    mma_tf32(acc[mt][nt], Ah[mt][0], Ah[mt][1], Ah[mt][2],
                             Ah[mt][3], bh0, bh1);
                }
            }
        }
        __syncthreads();
    }

#pragma unroll
    for (int mt = 0; mt < 2; mt++) {
        const int row0 = bm + wm * 32 + mt * 16 + g;
        const int row1 = row0 + 8;
        float s0a[4], s1a[4], d0a[4], d1a[4];
#pragma unroll
        for (int nt = 0; nt < 4; nt++) {
            const int h = wn * 4 + nt;
            const int col = h * 8 + tig * 2;
            float4 a = acc[mt][nt];
            if (row0 < N)
                *(float2*)&g_xl[(size_t)row0 * 64 + col] = make_float2(a.x, a.y);
            if (row1 < N)
                *(float2*)&g_xl[(size_t)row1 * 64 + col] = make_float2(a.z, a.w);

            float2 asv = make_float2(__ldg(att_s + h * 8 + 2 * tig),
                                     __ldg(att_s + h * 8 + 2 * tig + 1));
            float2 adv = make_float2(__ldg(att_d + h * 8 + 2 * tig),
                                     __ldg(att_d + h * 8 + 2 * tig + 1));
            float s0 = a.x * asv.x + a.y * asv.y;
            float s1 = a.z * asv.x + a.w * asv.y;
            float d0 = a.x * adv.x + a.y * adv.y;
            float d1 = a.z * adv.x + a.w * adv.y;
#pragma unroll
            for (int off = 1; off < 4; off <<= 1) {
                s0 += __shfl_xor_sync(0xffffffffu, s0, off);
                s1 += __shfl_xor_sync(0xffffffffu, s1, off);
                d0 += __shfl_xor_sync(0xffffffffu, d0, off);
                d1 += __shfl_xor_sync(0xffffffffu, d1, off);
            }
            s0a[nt] = s0; s1a[nt] = s1; d0a[nt] = d0; d1a[nt] = d1;
        }
        if (tig == 0) {
            if (row0 < N) {
                *(float4*)&g_as1[row0 * 8 + wn * 4] =
                    make_float4(s0a[0], s0a[1], s0a[2], s0a[3]);
                *(float4*)&g_ad1[row0 * 8 + wn * 4] =
                    make_float4(d0a[0], d0a[1], d0a[2], d0a[3]);
            }
            if (row1 < N) {
                *(float4*)&g_as1[row1 * 8 + wn * 4] =
                    make_float4(s1a[0], s1a[1], s1a[2], s1a[3]);
                *(float4*)&g_ad1[row1 * 8 + wn * 4] =
                    make_float4(d1a[0], d1a[1], d1a[2], d1a[3]);
            }
        }
    }
}

// ---- layer1 aggregation + bias + layer2 GEMM + layer2 logits (fused) ------
__global__ __launch_bounds__(256) void k_agg1(const float* __restrict__ b1,
                                              const float* __restrict__ W2,
                                              const float* __restrict__ atts2,
                                              const float* __restrict__ attd2,
                                              int N) {
    __shared__ float sh[8][64];
    int warp = (blockIdx.x * blockDim.x + threadIdx.x) >> 5;
    int wl = (threadIdx.x >> 5);
    int lane = threadIdx.x & 31;
    if (warp >= N) return;
    const int d = warp;
    const int h = lane >> 2;
    const float ad = g_ad1[d * 8 + h];

    float w = __expf(leaky02(g_as1[d * 8 + h] + ad));
    float2 v = *(const float2*)&g_xl[(size_t)d * 64 + lane * 2];
    float nx = w * v.x, ny = w * v.y;
    float den = ((lane & 3) == 0) ? w : 0.f;

    const int e1 = g_rptr[d + 1];
#pragma unroll 4
    for (int e = g_rptr[d]; e < e1; e++) {
        int s = g_col[e];
        float we = __expf(leaky02(g_as1[s * 8 + h] + ad));
        float2 xs = *(const float2*)&g_xl[(size_t)s * 64 + lane * 2];
        nx += we * xs.x;
        ny += we * xs.y;
        if ((lane & 3) == 0) den += we;
    }
    float dfull = __shfl_sync(0xffffffffu, den, lane & ~3) + 1e-16f;
    float inv = 1.f / dfull;

    // h row (bias folded) into per-warp smem
    sh[wl][lane * 2]     = nx * inv + __ldg(b1 + lane * 2);
    sh[wl][lane * 2 + 1] = ny * inv + __ldg(b1 + lane * 2 + 1);
    __syncwarp();

    // layer2 GEMM: all 32 lanes (lane = 16*half + col), halves split j-range
    const int c = lane & 15;
    const int jb = (lane >> 4) * 32;
    float y = 0.f;
#pragma unroll
    for (int j2 = 0; j2 < 32; j2++) {
        int j = jb + j2;
        y += sh[wl][j] * __ldg(W2 + j * 16 + c);
    }
    y += __shfl_xor_sync(0xffffffffu, y, 16);   // both halves now hold full y

    if (lane < 16) g_hl2[(size_t)d * 16 + c] = y;

    float pa = y * __ldg(atts2 + c);
    float pd = y * __ldg(attd2 + c);
#pragma unroll
    for (int off = 8; off >= 1; off >>= 1) {
        pa += __shfl_xor_sync(0xffffffffu, pa, off);
        pd += __shfl_xor_sync(0xffffffffu, pd, off);
    }
    if (lane == 0) {
        g_as2[d] = pa;
        g_ad2[d] = pd;
    }
}

// ------ layer2 aggregation + bias + elu + log_softmax (16 lanes/node) ------
__global__ __launch_bounds__(256) void k_agg2(const float* __restrict__ b2,
                                              float* __restrict__ out, int N) {
    int gid = (blockIdx.x * blockDim.x + threadIdx.x) >> 4;
    int c = threadIdx.x & 15;
    bool valid = gid < N;
    const int d = valid ? gid : 0;
    const float ad = g_ad2[d];

    float w = __expf(leaky02(g_as2[d] + ad));
    float num = w * g_hl2[(size_t)d * 16 + c];
    float den = w;

    const int e1 = g_rptr[d + 1];
#pragma unroll 4
    for (int e = g_rptr[d]; e < e1; e++) {
        int s = g_col[e];
        float we = __expf(leaky02(g_as2[s] + ad));
        num += we * g_hl2[(size_t)s * 16 + c];
        den += we;
    }
    float x = num / (den + 1e-16f) + __ldg(b2 + c);
    x = (x > 0.f) ? x : (__expf(x) - 1.f);

    float m = x;
#pragma unroll
    for (int off = 1; off < 16; off <<= 1)
        m = fmaxf(m, __shfl_xor_sync(0xffffffffu, m, off));
    float ssum = __expf(x - m);
#pragma unroll
    for (int off = 1; off < 16; off <<= 1)
        ssum += __shfl_xor_sync(0xffffffffu, ssum, off);
    if (valid) out[(size_t)d * 16 + c] = x - m - __logf(ssum);
}

// ---------------------------------------------------------------------------
extern "C" void kernel_launch(void* const* d_in, const int* in_sizes, int n_in,
                              void* d_out, int out_size) {
    const float* x     = (const float*)d_in[0];
    const int*   ei    = (const int*)d_in[1];
    const float* W1    = (const float*)d_in[2];
    const float* atts1 = (const float*)d_in[3];
    const float* attd1 = (const float*)d_in[4];
    const float* b1    = (const float*)d_in[5];
    const float* W2    = (const float*)d_in[6];
    const float* atts2 = (const float*)d_in[7];
    const float* attd2 = (const float*)d_in[8];
    const float* b2    = (const float*)d_in[9];
    float* out = (float*)d_out;

    const int N = in_sizes[0] / 512;
    const int E = in_sizes[1] / 2;
    const int ntiles = (N + 1023) >> 10;

    static cudaStream_t s_csr = nullptr;
    static cudaEvent_t ev_fork = nullptr, ev_join = nullptr;
    if (!s_csr) {
        cudaFuncSetAttribute(k_gemm1, cudaFuncAttributeMaxDynamicSharedMemorySize,
                             G1_SMEM_BYTES);
        cudaStreamCreateWithFlags(&s_csr, cudaStreamNonBlocking);
        cudaEventCreateWithFlags(&ev_fork, cudaEventDisableTiming);
        cudaEventCreateWithFlags(&ev_join, cudaEventDisableTiming);
    }

    // fork: CSR build on s_csr, GEMM1 on the main stream
    cudaEventRecord(ev_fork, 0);
    cudaStreamWaitEvent(s_csr, ev_fork, 0);

    k_hist<<<(E / 4 + 255) / 256, 256, 0, s_csr>>>(ei, E);
    k_scan1<<<ntiles, 1024, 0, s_csr>>>(N);
    k_scan3<<<(N + 255) / 256, 256, 0, s_csr>>>(N, E, ntiles);
    k_scatter<<<(E / 4 + 255) / 256, 256, 0, s_csr>>>(ei, E, N);
    cudaEventRecord(ev_join, s_csr);

    k_gemm1<<<(N + 127) / 128, 256, G1_SMEM_BYTES>>>(x, W1, atts1, attd1, N);

    // join: aggregation needs both CSR and GEMM1
    cudaStreamWaitEvent(0, ev_join, 0);

    k_agg1<<<(N * 32 + 255) / 256, 256>>>(b1, W2, atts2, attd2, N);
    k_agg2<<<(N * 16 + 255) / 256, 256>>>(b2, out, N);
}

// round 9
// speedup vs baseline: 1.9245x; 1.0063x over previous
#include <cuda_runtime.h>
#include <cuda_fp16.h>
#include <cstdint>

// ---------------------------------------------------------------------------
// GATNet 2-layer GAT, N=50000, E=800000 (+self loops).
// GEMM1 = 3xTF32 tensor-core (128x64 tile) with fused attention logits.
// Messages (xl) stored fp16 (attention weights stay fp32) -> half the L2
// gather traffic in agg1. CSR built on a side stream overlapped with GEMM1.
// agg1 fuses layer-1 aggregation + bias + layer-2 GEMM + layer-2 logits.
// ---------------------------------------------------------------------------

#define NMAX 50000
#define EMAX 800000

__device__ __align__(16) __half2 g_xlh[NMAX * 32];   // xl as half2 pairs
__device__ __align__(16) float g_as1[NMAX * 8];
__device__ __align__(16) float g_ad1[NMAX * 8];
__device__ __align__(16) float g_hl2[NMAX * 16];
__device__ float g_as2[NMAX];
__device__ float g_ad2[NMAX];

__device__ int g_cnt [NMAX];   // zero at module load; re-zeroed by k_scatter
__device__ int g_inc [NMAX];
__device__ int g_bsum[64];
__device__ int g_rptr[NMAX + 1];
__device__ int g_rank[EMAX];
__device__ int g_col [EMAX];

__device__ __forceinline__ float leaky02(float a) { return fmaxf(a, 0.2f * a); }

__device__ __forceinline__ float tf32r(float x) {
    uint32_t u;
    asm("cvt.rna.tf32.f32 %0, %1;" : "=r"(u) : "f"(x));
    return __uint_as_float(u);
}

__device__ __forceinline__ void mma_tf32(float4& c, uint32_t a0, uint32_t a1,
                                         uint32_t a2, uint32_t a3,
                                         uint32_t b0, uint32_t b1) {
    asm volatile(
        "mma.sync.aligned.m16n8k8.row.col.f32.tf32.tf32.f32 "
        "{%0,%1,%2,%3}, {%4,%5,%6,%7}, {%8,%9}, {%0,%1,%2,%3};\n"
        : "+f"(c.x), "+f"(c.y), "+f"(c.z), "+f"(c.w)
        : "r"(a0), "r"(a1), "r"(a2), "r"(a3), "r"(b0), "r"(b1));
}

// ----------------------------- CSR construction ----------------------------
__global__ void k_hist(const int* __restrict__ ei, int E) {
    int base = (blockIdx.x * blockDim.x + threadIdx.x) * 4;
    if (base >= E) return;
    int m = E - base; if (m > 4) m = 4;
    int d[4];
#pragma unroll
    for (int i = 0; i < 4; i++) if (i < m) d[i] = ei[E + base + i];
#pragma unroll
    for (int i = 0; i < 4; i++)
        if (i < m) g_rank[base + i] = atomicAdd(&g_cnt[d[i]], 1);
}

__global__ __launch_bounds__(1024) void k_scan1(int N) {
    __shared__ int sw[32];
    int t = threadIdx.x, i = blockIdx.x * 1024 + t;
    int lane = t & 31, wid = t >> 5;
    int s = (i < N) ? g_cnt[i] : 0;
#pragma unroll
    for (int o = 1; o < 32; o <<= 1) {
        int u = __shfl_up_sync(0xffffffffu, s, o);
        if (lane >= o) s += u;
    }
    if (lane == 31) sw[wid] = s;
    __syncthreads();
    if (wid == 0) {
        int ws = sw[lane];
#pragma unroll
        for (int o = 1; o < 32; o <<= 1) {
            int u = __shfl_up_sync(0xffffffffu, ws, o);
            if (lane >= o) ws += u;
        }
        sw[lane] = ws;
    }
    __syncthreads();
    int incl = s + (wid ? sw[wid - 1] : 0);
    if (i < N) g_inc[i] = incl;
    if (t == 1023) g_bsum[blockIdx.x] = incl;
}

__global__ void k_scan3(int N, int E, int ntiles) {
    __shared__ int sh[64];
    int t = threadIdx.x;
    if (t < 32) {
        int a = (t < ntiles) ? g_bsum[t] : 0;
        int b = (t + 32 < ntiles) ? g_bsum[t + 32] : 0;
#pragma unroll
        for (int o = 1; o < 32; o <<= 1) {
            int u = __shfl_up_sync(0xffffffffu, a, o);
            if (t >= o) a += u;
        }
        int tot = __shfl_sync(0xffffffffu, a, 31);
#pragma unroll
        for (int o = 1; o < 32; o <<= 1) {
            int u = __shfl_up_sync(0xffffffffu, b, o);
            if (t >= o) b += u;
        }
        sh[t] = a;
        sh[t + 32] = b + tot;
    }
    __syncthreads();
    int i = blockIdx.x * blockDim.x + t;
    if (i < N) {
        int blk = i >> 10;
        int excl = blk ? sh[blk - 1] : 0;
        g_rptr[i] = g_inc[i] - g_cnt[i] + excl;
    }
    if (i == 0) g_rptr[N] = E;
}

__global__ void k_scatter(const int* __restrict__ ei, int E, int N) {
    int tid = blockIdx.x * blockDim.x + threadIdx.x;
    if (tid < N) g_cnt[tid] = 0;
    int base = tid * 4;
    if (base >= E) return;
    int m = E - base; if (m > 4) m = 4;
    int d[4], s[4], r[4], rp[4];
#pragma unroll
    for (int i = 0; i < 4; i++)
        if (i < m) { d[i] = ei[E + base + i]; s[i] = ei[base + i]; }
#pragma unroll
    for (int i = 0; i < 4; i++) if (i < m) r[i] = g_rank[base + i];
#pragma unroll
    for (int i = 0; i < 4; i++) if (i < m) rp[i] = g_rptr[d[i]];
#pragma unroll
    for (int i = 0; i < 4; i++) if (i < m) g_col[rp[i] + r[i]] = s[i];
}

// --------------- GEMM1 (3xTF32 MMA) + fused node1 logits -------------------
#define G1_SMEM_BYTES (2 * 128 * 36 * 4 + 2 * 32 * 72 * 4)  // 55296

__global__ __launch_bounds__(256) void k_gemm1(const float* __restrict__ X,
                                               const float* __restrict__ W,
                                               const float* __restrict__ att_s,
                                               const float* __restrict__ att_d,
                                               int N) {
    extern __shared__ float smem[];
    float (*sAh)[36] = (float(*)[36])(smem);
    float (*sAl)[36] = (float(*)[36])(smem + 128 * 36);
    float (*sBh)[72] = (float(*)[72])(smem + 2 * 128 * 36);
    float (*sBl)[72] = (float(*)[72])(smem + 2 * 128 * 36 + 32 * 72);

    const int tid  = threadIdx.x;
    const int bm   = blockIdx.x * 128;
    const int warp = tid >> 5, lane = tid & 31;
    const int wm   = warp >> 1, wn = warp & 1;
    const int g    = lane >> 2, tig = lane & 3;

    const int ar = tid >> 1, ah = (tid & 1) * 16;
    const int bk = tid >> 3, bq = (tid & 7) * 8;

    int axr = bm + ar;
    if (axr >= N) axr = N - 1;
    const float4* Xr = (const float4*)(X + (size_t)axr * 512);

    float4 acc[2][4];
#pragma unroll
    for (int i = 0; i < 2; i++)
#pragma unroll
        for (int j = 0; j < 4; j++) acc[i][j] = make_float4(0.f, 0.f, 0.f, 0.f);

    float4 ra[4], rb[2];
#pragma unroll
    for (int i = 0; i < 4; i++) ra[i] = Xr[(ah >> 2) + i];
#pragma unroll
    for (int i = 0; i < 2; i++)
        rb[i] = ((const float4*)(W + (size_t)bk * 64 + bq))[i];

    for (int ks = 0; ks < 16; ks++) {
#pragma unroll
        for (int i = 0; i < 4; i++) {
            float4 h4 = make_float4(tf32r(ra[i].x), tf32r(ra[i].y),
                                    tf32r(ra[i].z), tf32r(ra[i].w));
            float4 l4 = make_float4(tf32r(ra[i].x - h4.x), tf32r(ra[i].y - h4.y),
                                    tf32r(ra[i].z - h4.z), tf32r(ra[i].w - h4.w));
            *(float4*)&sAh[ar][ah + i * 4] = h4;
            *(float4*)&sAl[ar][ah + i * 4] = l4;
        }
#pragma unroll
        for (int i = 0; i < 2; i++) {
            float4 h4 = make_float4(tf32r(rb[i].x), tf32r(rb[i].y),
                                    tf32r(rb[i].z), tf32r(rb[i].w));
            float4 l4 = make_float4(tf32r(rb[i].x - h4.x), tf32r(rb[i].y - h4.y),
                                    tf32r(rb[i].z - h4.z), tf32r(rb[i].w - h4.w));
            *(float4*)&sBh[bk][bq + i * 4] = h4;
            *(float4*)&sBl[bk][bq + i * 4] = l4;
        }
        __syncthreads();
        if (ks < 15) {
            int k0 = (ks + 1) * 32;
#pragma unroll
            for (int i = 0; i < 4; i++) ra[i] = Xr[((k0 + ah) >> 2) + i];
#pragma unroll
            for (int i = 0; i < 2; i++)
                rb[i] = ((const float4*)(W + (size_t)(k0 + bk) * 64 + bq))[i];
        }
#pragma unroll
        for (int ksub = 0; ksub < 4; ksub++) {
            const int kc = ksub * 8;
            uint32_t Ah[2][4], Al[2][4];
#pragma unroll
            for (int mt = 0; mt < 2; mt++) {
                const int r0 = wm * 32 + mt * 16 + g, r1 = r0 + 8;
                Ah[mt][0] = __float_as_uint(sAh[r0][kc + tig]);
                Ah[mt][1] = __float_as_uint(sAh[r1][kc + tig]);
                Ah[mt][2] = __float_as_uint(sAh[r0][kc + tig + 4]);
                Ah[mt][3] = __float_as_uint(sAh[r1][kc + tig + 4]);
                Al[mt][0] = __float_as_uint(sAl[r0][kc + tig]);
                Al[mt][1] = __float_as_uint(sAl[r1][kc + tig]);
                Al[mt][2] = __float_as_uint(sAl[r0][kc + tig + 4]);
                Al[mt][3] = __float_as_uint(sAl[r1][kc + tig + 4]);
            }
#pragma unroll
            for (int nt = 0; nt < 4; nt++) {
                const int nc = wn * 32 + nt * 8 + g;
                uint32_t bh0 = __float_as_uint(sBh[kc + tig][nc]);
                uint32_t bh1 = __float_as_uint(sBh[kc + tig + 4][nc]);
                uint32_t bl0 = __float_as_uint(sBl[kc + tig][nc]);
                uint32_t bl1 = __float_as_uint(sBl[kc + tig + 4][nc]);
#pragma unroll
                for (int mt = 0; mt < 2; mt++) {
                    mma_tf32(acc[mt][nt], Al[mt][0], Al[mt][1], Al[mt][2],
                             Al[mt][3], bh0, bh1);
                    mma_tf32(acc[mt][nt], Ah[mt][0], Ah[mt][1], Ah[mt][2],
                             Ah[mt][3], bl0, bl1);
                    mma_tf32(acc[mt][nt], Ah[mt][0], Ah[mt][1], Ah[mt][2],
                             Ah[mt][3], bh0, bh1);
                }
            }
        }
        __syncthreads();
    }

#pragma unroll
    for (int mt = 0; mt < 2; mt++) {
        const int row0 = bm + wm * 32 + mt * 16 + g;
        const int row1 = row0 + 8;
        float s0a[4], s1a[4], d0a[4], d1a[4];
#pragma unroll
        for (int nt = 0; nt < 4; nt++) {
            const int h = wn * 4 + nt;
            const int colh = h * 4 + tig;   // half2 index within row
            float4 a = acc[mt][nt];
            if (row0 < N)
                g_xlh[(size_t)row0 * 32 + colh] = __floats2half2_rn(a.x, a.y);
            if (row1 < N)
                g_xlh[(size_t)row1 * 32 + colh] = __floats2half2_rn(a.z, a.w);

            float2 asv = make_float2(__ldg(att_s + h * 8 + 2 * tig),
                                     __ldg(att_s + h * 8 + 2 * tig + 1));
            float2 adv = make_float2(__ldg(att_d + h * 8 + 2 * tig),
                                     __ldg(att_d + h * 8 + 2 * tig + 1));
            float s0 = a.x * asv.x + a.y * asv.y;
            float s1 = a.z * asv.x + a.w * asv.y;
            float d0 = a.x * adv.x + a.y * adv.y;
            float d1 = a.z * adv.x + a.w * adv.y;
#pragma unroll
            for (int off = 1; off < 4; off <<= 1) {
                s0 += __shfl_xor_sync(0xffffffffu, s0, off);
                s1 += __shfl_xor_sync(0xffffffffu, s1, off);
                d0 += __shfl_xor_sync(0xffffffffu, d0, off);
                d1 += __shfl_xor_sync(0xffffffffu, d1, off);
            }
            s0a[nt] = s0; s1a[nt] = s1; d0a[nt] = d0; d1a[nt] = d1;
        }
        if (tig == 0) {
            if (row0 < N) {
                *(float4*)&g_as1[row0 * 8 + wn * 4] =
                    make_float4(s0a[0], s0a[1], s0a[2], s0a[3]);
                *(float4*)&g_ad1[row0 * 8 + wn * 4] =
                    make_float4(d0a[0], d0a[1], d0a[2], d0a[3]);
            }
            if (row1 < N) {
                *(float4*)&g_as1[row1 * 8 + wn * 4] =
                    make_float4(s1a[0], s1a[1], s1a[2], s1a[3]);
                *(float4*)&g_ad1[row1 * 8 + wn * 4] =
                    make_float4(d1a[0], d1a[1], d1a[2], d1a[3]);
            }
        }
    }
}

// ---- layer1 aggregation + bias + layer2 GEMM + layer2 logits (fused) ------
// Warp per dst node; messages gathered as half2 (weights fp32).
__global__ __launch_bounds__(256) void k_agg1(const float* __restrict__ b1,
                                              const float* __restrict__ W2,
                                              const float* __restrict__ atts2,
                                              const float* __restrict__ attd2,
                                              int N) {
    __shared__ float sh[8][64];
    int warp = (blockIdx.x * blockDim.x + threadIdx.x) >> 5;
    int wl = (threadIdx.x >> 5);
    int lane = threadIdx.x & 31;
    if (warp >= N) return;
    const int d = warp;
    const int h = lane >> 2;
    const float ad = g_ad1[d * 8 + h];

    float w = __expf(leaky02(g_as1[d * 8 + h] + ad));
    float2 v = __half22float2(g_xlh[(size_t)d * 32 + lane]);
    float nx = w * v.x, ny = w * v.y;
    float den = ((lane & 3) == 0) ? w : 0.f;

    const int e1 = g_rptr[d + 1];
#pragma unroll 4
    for (int e = g_rptr[d]; e < e1; e++) {
        int s = g_col[e];
        float we = __expf(leaky02(g_as1[s * 8 + h] + ad));
        float2 xs = __half22float2(g_xlh[(size_t)s * 32 + lane]);
        nx += we * xs.x;
        ny += we * xs.y;
        if ((lane & 3) == 0) den += we;
    }
    float dfull = __shfl_sync(0xffffffffu, den, lane & ~3) + 1e-16f;
    float inv = 1.f / dfull;

    // h row (bias folded) into per-warp smem
    sh[wl][lane * 2]     = nx * inv + __ldg(b1 + lane * 2);
    sh[wl][lane * 2 + 1] = ny * inv + __ldg(b1 + lane * 2 + 1);
    __syncwarp();

    // layer2 GEMM: all 32 lanes (lane = 16*half + col), halves split j-range
    const int c = lane & 15;
    const int jb = (lane >> 4) * 32;
    float y = 0.f;
#pragma unroll
    for (int j2 = 0; j2 < 32; j2++) {
        int j = jb + j2;
        y += sh[wl][j] * __ldg(W2 + j * 16 + c);
    }
    y += __shfl_xor_sync(0xffffffffu, y, 16);

    if (lane < 16) g_hl2[(size_t)d * 16 + c] = y;

    float pa = y * __ldg(atts2 + c);
    float pd = y * __ldg(attd2 + c);
#pragma unroll
    for (int off = 8; off >= 1; off >>= 1) {
        pa += __shfl_xor_sync(0xffffffffu, pa, off);
        pd += __shfl_xor_sync(0xffffffffu, pd, off);
    }
    if (lane == 0) {
        g_as2[d] = pa;
        g_ad2[d] = pd;
    }
}

// ------ layer2 aggregation + bias + elu + log_softmax (16 lanes/node) ------
__global__ __launch_bounds__(256) void k_agg2(const float* __restrict__ b2,
                                              float* __restrict__ out, int N) {
    int gid = (blockIdx.x * blockDim.x + threadIdx.x) >> 4;
    int c = threadIdx.x & 15;
    bool valid = gid < N;
    const int d = valid ? gid : 0;
    const float ad = g_ad2[d];

    float w = __expf(leaky02(g_as2[d] + ad));
    float num = w * g_hl2[(size_t)d * 16 + c];
    float den = w;

    const int e1 = g_rptr[d + 1];
#pragma unroll 4
    for (int e = g_rptr[d]; e < e1; e++) {
        int s = g_col[e];
        float we = __expf(leaky02(g_as2[s] + ad));
        num += we * g_hl2[(size_t)s * 16 + c];
        den += we;
    }
    float x = num / (den + 1e-16f) + __ldg(b2 + c);
    x = (x > 0.f) ? x : (__expf(x) - 1.f);

    float m = x;
#pragma unroll
    for (int off = 1; off < 16; off <<= 1)
        m = fmaxf(m, __shfl_xor_sync(0xffffffffu, m, off));
    float ssum = __expf(x - m);
#pragma unroll
    for (int off = 1; off < 16; off <<= 1)
        ssum += __shfl_xor_sync(0xffffffffu, ssum, off);
    if (valid) out[(size_t)d * 16 + c] = x - m - __logf(ssum);
}

// ---------------------------------------------------------------------------
extern "C" void kernel_launch(void* const* d_in, const int* in_sizes, int n_in,
                              void* d_out, int out_size) {
    const float* x     = (const float*)d_in[0];
    const int*   ei    = (const int*)d_in[1];
    const float* W1    = (const float*)d_in[2];
    const float* atts1 = (const float*)d_in[3];
    const float* attd1 = (const float*)d_in[4];
    const float* b1    = (const float*)d_in[5];
    const float* W2    = (const float*)d_in[6];
    const float* atts2 = (const float*)d_in[7];
    const float* attd2 = (const float*)d_in[8];
    const float* b2    = (const float*)d_in[9];
    float* out = (float*)d_out;

    const int N = in_sizes[0] / 512;
    const int E = in_sizes[1] / 2;
    const int ntiles = (N + 1023) >> 10;

    static cudaStream_t s_csr = nullptr;
    static cudaEvent_t ev_fork = nullptr, ev_join = nullptr;
    if (!s_csr) {
        cudaFuncSetAttribute(k_gemm1, cudaFuncAttributeMaxDynamicSharedMemorySize,
                             G1_SMEM_BYTES);
        cudaStreamCreateWithFlags(&s_csr, cudaStreamNonBlocking);
        cudaEventCreateWithFlags(&ev_fork, cudaEventDisableTiming);
        cudaEventCreateWithFlags(&ev_join, cudaEventDisableTiming);
    }

    // fork: CSR build on s_csr, GEMM1 on the main stream
    cudaEventRecord(ev_fork, 0);
    cudaStreamWaitEvent(s_csr, ev_fork, 0);

    k_hist<<<(E / 4 + 255) / 256, 256, 0, s_csr>>>(ei, E);
    k_scan1<<<ntiles, 1024, 0, s_csr>>>(N);
    k_scan3<<<(N + 255) / 256, 256, 0, s_csr>>>(N, E, ntiles);
    k_scatter<<<(E / 4 + 255) / 256, 256, 0, s_csr>>>(ei, E, N);
    cudaEventRecord(ev_join, s_csr);

    k_gemm1<<<(N + 127) / 128, 256, G1_SMEM_BYTES>>>(x, W1, atts1, attd1, N);

    // join: aggregation needs both CSR and GEMM1
    cudaStreamWaitEvent(0, ev_join, 0);

    k_agg1<<<(N * 32 + 255) / 256, 256>>>(b1, W2, atts2, attd2, N);
    k_agg2<<<(N * 16 + 255) / 256, 256>>>(b2, out, N);
}